// round 1
// baseline (speedup 1.0000x reference)
#include <cuda_runtime.h>
#include <math.h>

#define S_LEN   2048
#define D_MODEL 4096
#define NH      32
#define NKV     8
#define HDIM    128
#define ATT_SCALE 0.08838834764831843f  // 128^-0.5

// Scratch (no allocation allowed): 32 + 8 + 8 + 32 = 80 MB
__device__ float g_Q[S_LEN * D_MODEL];
__device__ float g_K[S_LEN * NKV * HDIM];
__device__ float g_V[S_LEN * NKV * HDIM];
__device__ float g_attn[S_LEN * D_MODEL];

// ---------------------------------------------------------------------------
// C[M,N] = A[M,K] @ B[N,K]^T   (A row-major [M,K], B row-major [N,K])
// 128x128 tile, BK=16, 256 threads, 8x8 register micro-tile.
// Requires M%128==0, N%128==0, K%16==0 (true for all shapes here).
// ---------------------------------------------------------------------------
__global__ __launch_bounds__(256) void sgemm_tn(const float* __restrict__ A,
                                                const float* __restrict__ B,
                                                float* __restrict__ C,
                                                int M, int N, int K) {
    __shared__ float As[16][128];
    __shared__ float Bs[16][128];

    const int t  = threadIdx.x;
    const int m0 = blockIdx.y * 128;
    const int n0 = blockIdx.x * 128;
    const int tx = t & 15;
    const int ty = t >> 4;

    // tile-load mapping: 512 float4 per operand tile, 2 per thread
    const int lr0 = t >> 2;          // rows 0..63
    const int lr1 = (t >> 2) + 64;   // rows 64..127
    const int lc  = (t & 3) * 4;     // k-offset within tile (0,4,8,12)

    float acc[8][8];
#pragma unroll
    for (int i = 0; i < 8; i++)
#pragma unroll
        for (int j = 0; j < 8; j++) acc[i][j] = 0.f;

    for (int k0 = 0; k0 < K; k0 += 16) {
        float4 a0 = *(const float4*)(A + (size_t)(m0 + lr0) * K + k0 + lc);
        float4 a1 = *(const float4*)(A + (size_t)(m0 + lr1) * K + k0 + lc);
        float4 b0 = *(const float4*)(B + (size_t)(n0 + lr0) * K + k0 + lc);
        float4 b1 = *(const float4*)(B + (size_t)(n0 + lr1) * K + k0 + lc);

        As[lc + 0][lr0] = a0.x; As[lc + 1][lr0] = a0.y;
        As[lc + 2][lr0] = a0.z; As[lc + 3][lr0] = a0.w;
        As[lc + 0][lr1] = a1.x; As[lc + 1][lr1] = a1.y;
        As[lc + 2][lr1] = a1.z; As[lc + 3][lr1] = a1.w;
        Bs[lc + 0][lr0] = b0.x; Bs[lc + 1][lr0] = b0.y;
        Bs[lc + 2][lr0] = b0.z; Bs[lc + 3][lr0] = b0.w;
        Bs[lc + 0][lr1] = b1.x; Bs[lc + 1][lr1] = b1.y;
        Bs[lc + 2][lr1] = b1.z; Bs[lc + 3][lr1] = b1.w;
        __syncthreads();

#pragma unroll
        for (int k = 0; k < 16; k++) {
            float a[8], b[8];
            *(float4*)(a)     = *(const float4*)&As[k][ty * 8];
            *(float4*)(a + 4) = *(const float4*)&As[k][ty * 8 + 4];
            *(float4*)(b)     = *(const float4*)&Bs[k][tx * 8];
            *(float4*)(b + 4) = *(const float4*)&Bs[k][tx * 8 + 4];
#pragma unroll
            for (int i = 0; i < 8; i++)
#pragma unroll
                for (int j = 0; j < 8; j++) acc[i][j] += a[i] * b[j];
        }
        __syncthreads();
    }

#pragma unroll
    for (int i = 0; i < 8; i++) {
        float* cp = C + (size_t)(m0 + ty * 8 + i) * N + n0 + tx * 8;
        float4 v0 = make_float4(acc[i][0], acc[i][1], acc[i][2], acc[i][3]);
        float4 v1 = make_float4(acc[i][4], acc[i][5], acc[i][6], acc[i][7]);
        *(float4*)(cp)     = v0;
        *(float4*)(cp + 4) = v1;
    }
}

// ---------------------------------------------------------------------------
// RoPE, interleaved pairs: (d=2i, 2i+1), angle = cos/sin[s][i]
// t layout: [S, nheads*128]
// ---------------------------------------------------------------------------
__global__ void rope_kernel(float* __restrict__ t, const float* __restrict__ cosw,
                            const float* __restrict__ sinw, int nheads) {
    int idx = blockIdx.x * blockDim.x + threadIdx.x;
    int total = S_LEN * nheads * (HDIM / 2);
    if (idx >= total) return;
    int i = idx & 63;                  // HDIM/2 = 64
    int h = (idx >> 6) % nheads;
    int s = idx / (64 * nheads);
    float c  = cosw[s * 64 + i];
    float sn = sinw[s * 64 + i];
    float* p = t + (size_t)s * nheads * HDIM + h * HDIM + 2 * i;
    float t0 = p[0], t1 = p[1];
    p[0] = t0 * c - t1 * sn;
    p[1] = t0 * sn + t1 * c;
}

// ---------------------------------------------------------------------------
// Flash attention, fp32, causal, GQA (4 q heads per kv head).
// Block: 256 threads handles one (head, 64-row q tile).
// Smem layout (dynamic):
//   Qt [128][68] transposed Q (pre-scaled)
//   Kt [128][68] transposed K
//   Vs [64][128] row-major V
//   Ps [64][64]  probabilities
// ---------------------------------------------------------------------------
#define QK_STRIDE 68
#define FLASH_SMEM ((128 * QK_STRIDE * 2 + 64 * 128 + 64 * 64) * 4)

__global__ __launch_bounds__(256) void flash_kernel() {
    extern __shared__ float sm[];
    float* Qt = sm;
    float* Kt = sm + 128 * QK_STRIDE;
    float* Vs = Kt + 128 * QK_STRIDE;
    float* Ps = Vs + 64 * 128;

    const int t  = threadIdx.x;
    const int qt = blockIdx.x;          // q tile (64 rows)
    const int h  = blockIdx.y;
    const int kh = h >> 2;              // GQA: kv head
    const int q0 = qt * 64;
    const int tx = t & 15;
    const int ty = t >> 4;

    // load Q tile transposed + pre-scaled
    for (int li = t; li < 64 * 128; li += 256) {
        int r = li >> 7, d = li & 127;
        Qt[d * QK_STRIDE + r] =
            g_Q[(size_t)(q0 + r) * D_MODEL + h * HDIM + d] * ATT_SCALE;
    }

    float m_i[4], l_i[4], o[4][8];
#pragma unroll
    for (int i = 0; i < 4; i++) {
        m_i[i] = -1e30f; l_i[i] = 0.f;
#pragma unroll
        for (int j = 0; j < 8; j++) o[i][j] = 0.f;
    }

    for (int kt = 0; kt <= qt; kt++) {
        const int k0 = kt * 64;
        __syncthreads();   // Q visible (kt=0); Kt/Vs safe to overwrite (kt>0)
        for (int li = t; li < 64 * 128; li += 256) {
            int r = li >> 7, d = li & 127;
            Kt[d * QK_STRIDE + r] = g_K[(size_t)(k0 + r) * (NKV * HDIM) + kh * HDIM + d];
            Vs[r * 128 + d]       = g_V[(size_t)(k0 + r) * (NKV * HDIM) + kh * HDIM + d];
        }
        __syncthreads();

        // S[4][4] = (Q*scale) @ K^T  for rows ty*4+i, cols tx*4+j
        float sacc[4][4];
#pragma unroll
        for (int i = 0; i < 4; i++)
#pragma unroll
            for (int j = 0; j < 4; j++) sacc[i][j] = 0.f;

#pragma unroll 4
        for (int d = 0; d < 128; d++) {
            float4 av = *(const float4*)&Qt[d * QK_STRIDE + ty * 4];
            float4 bv = *(const float4*)&Kt[d * QK_STRIDE + tx * 4];
            float a[4] = {av.x, av.y, av.z, av.w};
            float b[4] = {bv.x, bv.y, bv.z, bv.w};
#pragma unroll
            for (int i = 0; i < 4; i++)
#pragma unroll
                for (int j = 0; j < 4; j++) sacc[i][j] += a[i] * b[j];
        }

        // causal mask on the diagonal tile (matches reference -1e9 add)
        if (kt == qt) {
#pragma unroll
            for (int i = 0; i < 4; i++)
#pragma unroll
                for (int j = 0; j < 4; j++)
                    if (tx * 4 + j > ty * 4 + i) sacc[i][j] += -1e9f;
        }

        // online softmax update (row stats shared by 16 lanes via shfl)
#pragma unroll
        for (int i = 0; i < 4; i++) {
            float tm = fmaxf(fmaxf(sacc[i][0], sacc[i][1]),
                             fmaxf(sacc[i][2], sacc[i][3]));
#pragma unroll
            for (int off = 1; off < 16; off <<= 1)
                tm = fmaxf(tm, __shfl_xor_sync(0xffffffffu, tm, off));
            float mnew  = fmaxf(m_i[i], tm);
            float alpha = expf(m_i[i] - mnew);
            m_i[i] = mnew;

            float p0 = expf(sacc[i][0] - mnew);
            float p1 = expf(sacc[i][1] - mnew);
            float p2 = expf(sacc[i][2] - mnew);
            float p3 = expf(sacc[i][3] - mnew);
            *(float4*)&Ps[(ty * 4 + i) * 64 + tx * 4] = make_float4(p0, p1, p2, p3);
            float rs = p0 + p1 + p2 + p3;
#pragma unroll
            for (int off = 1; off < 16; off <<= 1)
                rs += __shfl_xor_sync(0xffffffffu, rs, off);
            l_i[i] = l_i[i] * alpha + rs;
#pragma unroll
            for (int j = 0; j < 8; j++) o[i][j] *= alpha;
        }
        __syncthreads();

        // O += P @ V   (rows ty*4+i, cols tx*8+j)
#pragma unroll 2
        for (int c = 0; c < 64; c++) {
            float p[4];
#pragma unroll
            for (int i = 0; i < 4; i++) p[i] = Ps[(ty * 4 + i) * 64 + c];
            float4 v0 = *(const float4*)&Vs[c * 128 + tx * 8];
            float4 v1 = *(const float4*)&Vs[c * 128 + tx * 8 + 4];
#pragma unroll
            for (int i = 0; i < 4; i++) {
                o[i][0] += p[i] * v0.x; o[i][1] += p[i] * v0.y;
                o[i][2] += p[i] * v0.z; o[i][3] += p[i] * v0.w;
                o[i][4] += p[i] * v1.x; o[i][5] += p[i] * v1.y;
                o[i][6] += p[i] * v1.z; o[i][7] += p[i] * v1.w;
            }
        }
    }

    // epilogue: normalize and store
#pragma unroll
    for (int i = 0; i < 4; i++) {
        float inv = 1.f / l_i[i];
        float* op = g_attn + (size_t)(q0 + ty * 4 + i) * D_MODEL + h * HDIM + tx * 8;
        float4 r0 = make_float4(o[i][0] * inv, o[i][1] * inv, o[i][2] * inv, o[i][3] * inv);
        float4 r1 = make_float4(o[i][4] * inv, o[i][5] * inv, o[i][6] * inv, o[i][7] * inv);
        *(float4*)(op)     = r0;
        *(float4*)(op + 4) = r1;
    }
}

// ---------------------------------------------------------------------------
extern "C" void kernel_launch(void* const* d_in, const int* in_sizes, int n_in,
                              void* d_out, int out_size) {
    const float* x  = (const float*)d_in[0];
    const float* fc = (const float*)d_in[1];
    const float* fs = (const float*)d_in[2];
    // d_in[3] = mask (unused; causal handled in-kernel with identical -1e9 semantics)
    const float* wq = (const float*)d_in[4];
    const float* wk = (const float*)d_in[5];
    const float* wv = (const float*)d_in[6];
    const float* wo = (const float*)d_in[7];
    float* out = (float*)d_out;

    float *qp, *kp, *vp, *ap;
    cudaGetSymbolAddress((void**)&qp, g_Q);
    cudaGetSymbolAddress((void**)&kp, g_K);
    cudaGetSymbolAddress((void**)&vp, g_V);
    cudaGetSymbolAddress((void**)&ap, g_attn);

    // QKV projections
    sgemm_tn<<<dim3(32, 16), 256>>>(x, wq, qp, S_LEN, NH * HDIM, D_MODEL);
    sgemm_tn<<<dim3(8, 16), 256>>>(x, wk, kp, S_LEN, NKV * HDIM, D_MODEL);
    sgemm_tn<<<dim3(8, 16), 256>>>(x, wv, vp, S_LEN, NKV * HDIM, D_MODEL);

    // RoPE on Q and K
    rope_kernel<<<(S_LEN * NH * 64 + 255) / 256, 256>>>(qp, fc, fs, NH);
    rope_kernel<<<(S_LEN * NKV * 64 + 255) / 256, 256>>>(kp, fc, fs, NKV);

    // Flash attention
    cudaFuncSetAttribute((const void*)flash_kernel,
                         cudaFuncAttributeMaxDynamicSharedMemorySize, FLASH_SMEM);
    flash_kernel<<<dim3(32, 32), 256, FLASH_SMEM>>>();

    // Output projection
    sgemm_tn<<<dim3(32, 16), 256>>>(ap, wo, out, S_LEN, D_MODEL, D_MODEL);
}

// round 2
// speedup vs baseline: 1.8865x; 1.8865x over previous
#include <cuda_runtime.h>
#include <cuda_fp16.h>
#include <math.h>
#include <stdint.h>

#define S_LEN   2048
#define D_MODEL 4096
#define NH      32
#define NKV     8
#define HDIM    128
#define ATT_SCALE 0.08838834764831843f  // 128^-0.5

// ---------------- static scratch (allocation forbidden) --------------------
__device__ float g_Q[S_LEN * D_MODEL];
__device__ float g_K[S_LEN * NKV * HDIM];
__device__ float g_V[S_LEN * NKV * HDIM];
__device__ float g_attn[S_LEN * D_MODEL];

// fp16 split (hi/lo) buffers
__device__ __half g_xh[S_LEN * D_MODEL],      g_xl[S_LEN * D_MODEL];
__device__ __half g_wqh[D_MODEL * D_MODEL],   g_wql[D_MODEL * D_MODEL];
__device__ __half g_wkh[NKV * HDIM * D_MODEL], g_wkl[NKV * HDIM * D_MODEL];
__device__ __half g_wvh[NKV * HDIM * D_MODEL], g_wvl[NKV * HDIM * D_MODEL];
__device__ __half g_woh[D_MODEL * D_MODEL],   g_wol[D_MODEL * D_MODEL];
__device__ __half g_ah[S_LEN * D_MODEL],      g_al[S_LEN * D_MODEL];

// ---------------------------------------------------------------------------
// split fp32 -> fp16 hi + fp16 lo  (a ~= hi + lo to ~2^-22 rel)
// ---------------------------------------------------------------------------
__global__ void split_kernel(const float* __restrict__ in,
                             __half* __restrict__ hi, __half* __restrict__ lo,
                             int n) {
    int i = blockIdx.x * blockDim.x + threadIdx.x;
    if (i >= n) return;
    float a = in[i];
    __half h = __float2half_rn(a);
    float r = a - __half2float(h);
    hi[i] = h;
    lo[i] = __float2half_rn(r);
}

// ---------------------------------------------------------------------------
// HGEMM with fp16 2-term split, fp32 accumulate.
// C[M,N] = A[M,K] @ B[N,K]^T   using (Ah+Al)(Bh+Bl) ~= AhBh + AhBl + AlBh
// 128x128x32 tiles, 256 threads (8 warps, 32x64 warp tiles), cp.async
// double buffering, XOR-swizzled smem for conflict-free ldmatrix.
// Requires M%128==0, N%128==0, K%32==0.
// ---------------------------------------------------------------------------
__device__ __forceinline__ void cp16(uint32_t dst, const void* src) {
    asm volatile("cp.async.cg.shared.global [%0], [%1], 16;\n"
                 :: "r"(dst), "l"(src));
}

#define LDSM4(R0, R1, R2, R3, ADDR)                                          \
    asm volatile("ldmatrix.sync.aligned.m8n8.x4.shared.b16 {%0,%1,%2,%3},[%4];" \
                 : "=r"(R0), "=r"(R1), "=r"(R2), "=r"(R3) : "r"(ADDR))

#define MMA16816(C, A, B0, B1)                                               \
    asm volatile("mma.sync.aligned.m16n8k16.row.col.f32.f16.f16.f32 "        \
                 "{%0,%1,%2,%3},{%4,%5,%6,%7},{%8,%9},{%0,%1,%2,%3};"        \
                 : "+f"((C)[0]), "+f"((C)[1]), "+f"((C)[2]), "+f"((C)[3])    \
                 : "r"((A)[0]), "r"((A)[1]), "r"((A)[2]), "r"((A)[3]),       \
                   "r"(B0), "r"(B1))

#define HGEMM_SMEM 65536  // 2 stages * (16KB A + 16KB B)

__global__ __launch_bounds__(256, 1)
void hgemm_split(const __half* __restrict__ Ah, const __half* __restrict__ Al,
                 const __half* __restrict__ Bh, const __half* __restrict__ Bl,
                 float* __restrict__ C, int M, int N, int K) {
    extern __shared__ __half sm[];
    const uint32_t sbase = (uint32_t)__cvta_generic_to_shared(sm);

    const int t    = threadIdx.x;
    const int m0   = blockIdx.y * 128;
    const int n0   = blockIdx.x * 128;
    const int warp = t >> 5;
    const int lane = t & 31;
    const int wm   = (warp >> 1) * 32;   // warp m offset (4 rows of warps)
    const int wn   = (warp & 1) * 64;    // warp n offset (2 cols of warps)

    // ldmatrix lane decomposition
    const int a_mloc = lane & 15;            // row within 16-row mma tile
    const int a_gsel = lane >> 4;            // k-granule select (0/1)
    const int b_nloc = (lane & 7) + ((lane & 16) >> 1);
    const int b_gsel = (lane >> 3) & 1;

    float acc[2][8][4];
#pragma unroll
    for (int mt = 0; mt < 2; mt++)
#pragma unroll
        for (int nt = 0; nt < 8; nt++)
#pragma unroll
            for (int r = 0; r < 4; r++) acc[mt][nt][r] = 0.f;

    // stage layout (bytes): A tile = 128 rows * 8 granules * 16B = 16384
    auto issue = [&](int k0, int buf) {
        uint32_t abase = sbase + buf * 32768;
        uint32_t bbase = abase + 16384;
#pragma unroll
        for (int i = 0; i < 4; i++) {
            int ga = t + i * 256;
            int m = ga >> 3, sg = ga & 7;   // sg: 0-3 hi granules, 4-7 lo
            const __half* src = (sg < 4 ? Ah : Al)
                              + (size_t)(m0 + m) * K + k0 + (sg & 3) * 8;
            cp16(abase + m * 128 + ((sg ^ (m & 7)) << 4), src);
        }
#pragma unroll
        for (int i = 0; i < 4; i++) {
            int ga = t + i * 256;
            int n = ga >> 3, sg = ga & 7;
            const __half* src = (sg < 4 ? Bh : Bl)
                              + (size_t)(n0 + n) * K + k0 + (sg & 3) * 8;
            cp16(bbase + n * 128 + ((sg ^ (n & 7)) << 4), src);
        }
    };

    const int NIT = K >> 5;
    issue(0, 0);
    asm volatile("cp.async.commit_group;");

    for (int it = 0; it < NIT; it++) {
        if (it + 1 < NIT) {
            issue((it + 1) << 5, (it + 1) & 1);
            asm volatile("cp.async.commit_group;");
            asm volatile("cp.async.wait_group 1;");
        } else {
            asm volatile("cp.async.wait_group 0;");
        }
        __syncthreads();

        const int buf = it & 1;
        const uint32_t abase = sbase + buf * 32768;
        const uint32_t bbase = abase + 16384;

#pragma unroll
        for (int c = 0; c < 2; c++) {       // two k16 chunks per k32 stage
            uint32_t ah[2][4], al[2][4], bb[4][4];
            // A hi fragments
#pragma unroll
            for (int mt = 0; mt < 2; mt++) {
                int m = wm + mt * 16 + a_mloc;
                int sg = 2 * c + a_gsel;
                LDSM4(ah[mt][0], ah[mt][1], ah[mt][2], ah[mt][3],
                      abase + m * 128 + ((sg ^ (m & 7)) << 4));
            }
            // B hi fragments (each x4 covers 2 n-tiles)
#pragma unroll
            for (int p = 0; p < 4; p++) {
                int n = wn + p * 16 + b_nloc;
                int sg = 2 * c + b_gsel;
                LDSM4(bb[p][0], bb[p][1], bb[p][2], bb[p][3],
                      bbase + n * 128 + ((sg ^ (n & 7)) << 4));
            }
            // hi * hi
#pragma unroll
            for (int mt = 0; mt < 2; mt++)
#pragma unroll
                for (int p = 0; p < 4; p++) {
                    MMA16816(acc[mt][2 * p],     ah[mt], bb[p][0], bb[p][1]);
                    MMA16816(acc[mt][2 * p + 1], ah[mt], bb[p][2], bb[p][3]);
                }
            // A lo fragments
#pragma unroll
            for (int mt = 0; mt < 2; mt++) {
                int m = wm + mt * 16 + a_mloc;
                int sg = 4 + 2 * c + a_gsel;
                LDSM4(al[mt][0], al[mt][1], al[mt][2], al[mt][3],
                      abase + m * 128 + ((sg ^ (m & 7)) << 4));
            }
            // lo * hi
#pragma unroll
            for (int mt = 0; mt < 2; mt++)
#pragma unroll
                for (int p = 0; p < 4; p++) {
                    MMA16816(acc[mt][2 * p],     al[mt], bb[p][0], bb[p][1]);
                    MMA16816(acc[mt][2 * p + 1], al[mt], bb[p][2], bb[p][3]);
                }
            // B lo fragments (overwrite bb)
#pragma unroll
            for (int p = 0; p < 4; p++) {
                int n = wn + p * 16 + b_nloc;
                int sg = 4 + 2 * c + b_gsel;
                LDSM4(bb[p][0], bb[p][1], bb[p][2], bb[p][3],
                      bbase + n * 128 + ((sg ^ (n & 7)) << 4));
            }
            // hi * lo
#pragma unroll
            for (int mt = 0; mt < 2; mt++)
#pragma unroll
                for (int p = 0; p < 4; p++) {
                    MMA16816(acc[mt][2 * p],     ah[mt], bb[p][0], bb[p][1]);
                    MMA16816(acc[mt][2 * p + 1], ah[mt], bb[p][2], bb[p][3]);
                }
        }
        __syncthreads();
    }

    // epilogue
#pragma unroll
    for (int mt = 0; mt < 2; mt++) {
        int r = m0 + wm + mt * 16 + (lane >> 2);
#pragma unroll
        for (int nt = 0; nt < 8; nt++) {
            int cc = n0 + wn + nt * 8 + (lane & 3) * 2;
            float* p0 = C + (size_t)r * N + cc;
            p0[0] = acc[mt][nt][0];
            p0[1] = acc[mt][nt][1];
            float* p1 = p0 + 8 * N;
            p1[0] = acc[mt][nt][2];
            p1[1] = acc[mt][nt][3];
        }
    }
}

// ---------------------------------------------------------------------------
// RoPE, interleaved pairs
// ---------------------------------------------------------------------------
__global__ void rope_kernel(float* __restrict__ t, const float* __restrict__ cosw,
                            const float* __restrict__ sinw, int nheads) {
    int idx = blockIdx.x * blockDim.x + threadIdx.x;
    int total = S_LEN * nheads * (HDIM / 2);
    if (idx >= total) return;
    int i = idx & 63;
    int h = (idx >> 6) % nheads;
    int s = idx / (64 * nheads);
    float c  = cosw[s * 64 + i];
    float sn = sinw[s * 64 + i];
    float* p = t + (size_t)s * nheads * HDIM + h * HDIM + 2 * i;
    float t0 = p[0], t1 = p[1];
    p[0] = t0 * c - t1 * sn;
    p[1] = t0 * sn + t1 * c;
}

// ---------------------------------------------------------------------------
// Flash attention, fp32, causal, GQA (unchanged from R1)
// ---------------------------------------------------------------------------
#define QK_STRIDE 68
#define FLASH_SMEM ((128 * QK_STRIDE * 2 + 64 * 128 + 64 * 64) * 4)

__global__ __launch_bounds__(256) void flash_kernel() {
    extern __shared__ float smf[];
    float* Qt = smf;
    float* Kt = smf + 128 * QK_STRIDE;
    float* Vs = Kt + 128 * QK_STRIDE;
    float* Ps = Vs + 64 * 128;

    const int t  = threadIdx.x;
    const int qt = blockIdx.x;
    const int h  = blockIdx.y;
    const int kh = h >> 2;
    const int q0 = qt * 64;
    const int tx = t & 15;
    const int ty = t >> 4;

    for (int li = t; li < 64 * 128; li += 256) {
        int r = li >> 7, d = li & 127;
        Qt[d * QK_STRIDE + r] =
            g_Q[(size_t)(q0 + r) * D_MODEL + h * HDIM + d] * ATT_SCALE;
    }

    float m_i[4], l_i[4], o[4][8];
#pragma unroll
    for (int i = 0; i < 4; i++) {
        m_i[i] = -1e30f; l_i[i] = 0.f;
#pragma unroll
        for (int j = 0; j < 8; j++) o[i][j] = 0.f;
    }

    for (int kt = 0; kt <= qt; kt++) {
        const int k0 = kt * 64;
        __syncthreads();
        for (int li = t; li < 64 * 128; li += 256) {
            int r = li >> 7, d = li & 127;
            Kt[d * QK_STRIDE + r] = g_K[(size_t)(k0 + r) * (NKV * HDIM) + kh * HDIM + d];
            Vs[r * 128 + d]       = g_V[(size_t)(k0 + r) * (NKV * HDIM) + kh * HDIM + d];
        }
        __syncthreads();

        float sacc[4][4];
#pragma unroll
        for (int i = 0; i < 4; i++)
#pragma unroll
            for (int j = 0; j < 4; j++) sacc[i][j] = 0.f;

#pragma unroll 4
        for (int d = 0; d < 128; d++) {
            float4 av = *(const float4*)&Qt[d * QK_STRIDE + ty * 4];
            float4 bv = *(const float4*)&Kt[d * QK_STRIDE + tx * 4];
            float a[4] = {av.x, av.y, av.z, av.w};
            float b[4] = {bv.x, bv.y, bv.z, bv.w};
#pragma unroll
            for (int i = 0; i < 4; i++)
#pragma unroll
                for (int j = 0; j < 4; j++) sacc[i][j] += a[i] * b[j];
        }

        if (kt == qt) {
#pragma unroll
            for (int i = 0; i < 4; i++)
#pragma unroll
                for (int j = 0; j < 4; j++)
                    if (tx * 4 + j > ty * 4 + i) sacc[i][j] += -1e9f;
        }

#pragma unroll
        for (int i = 0; i < 4; i++) {
            float tm = fmaxf(fmaxf(sacc[i][0], sacc[i][1]),
                             fmaxf(sacc[i][2], sacc[i][3]));
#pragma unroll
            for (int off = 1; off < 16; off <<= 1)
                tm = fmaxf(tm, __shfl_xor_sync(0xffffffffu, tm, off));
            float mnew  = fmaxf(m_i[i], tm);
            float alpha = expf(m_i[i] - mnew);
            m_i[i] = mnew;

            float p0 = expf(sacc[i][0] - mnew);
            float p1 = expf(sacc[i][1] - mnew);
            float p2 = expf(sacc[i][2] - mnew);
            float p3 = expf(sacc[i][3] - mnew);
            *(float4*)&Ps[(ty * 4 + i) * 64 + tx * 4] = make_float4(p0, p1, p2, p3);
            float rs = p0 + p1 + p2 + p3;
#pragma unroll
            for (int off = 1; off < 16; off <<= 1)
                rs += __shfl_xor_sync(0xffffffffu, rs, off);
            l_i[i] = l_i[i] * alpha + rs;
#pragma unroll
            for (int j = 0; j < 8; j++) o[i][j] *= alpha;
        }
        __syncthreads();

#pragma unroll 2
        for (int c = 0; c < 64; c++) {
            float p[4];
#pragma unroll
            for (int i = 0; i < 4; i++) p[i] = Ps[(ty * 4 + i) * 64 + c];
            float4 v0 = *(const float4*)&Vs[c * 128 + tx * 8];
            float4 v1 = *(const float4*)&Vs[c * 128 + tx * 8 + 4];
#pragma unroll
            for (int i = 0; i < 4; i++) {
                o[i][0] += p[i] * v0.x; o[i][1] += p[i] * v0.y;
                o[i][2] += p[i] * v0.z; o[i][3] += p[i] * v0.w;
                o[i][4] += p[i] * v1.x; o[i][5] += p[i] * v1.y;
                o[i][6] += p[i] * v1.z; o[i][7] += p[i] * v1.w;
            }
        }
    }

#pragma unroll
    for (int i = 0; i < 4; i++) {
        float inv = 1.f / l_i[i];
        float* op = g_attn + (size_t)(q0 + ty * 4 + i) * D_MODEL + h * HDIM + tx * 8;
        float4 r0 = make_float4(o[i][0] * inv, o[i][1] * inv, o[i][2] * inv, o[i][3] * inv);
        float4 r1 = make_float4(o[i][4] * inv, o[i][5] * inv, o[i][6] * inv, o[i][7] * inv);
        *(float4*)(op)     = r0;
        *(float4*)(op + 4) = r1;
    }
}

// ---------------------------------------------------------------------------
extern "C" void kernel_launch(void* const* d_in, const int* in_sizes, int n_in,
                              void* d_out, int out_size) {
    const float* x  = (const float*)d_in[0];
    const float* fc = (const float*)d_in[1];
    const float* fs = (const float*)d_in[2];
    const float* wq = (const float*)d_in[4];
    const float* wk = (const float*)d_in[5];
    const float* wv = (const float*)d_in[6];
    const float* wo = (const float*)d_in[7];
    float* out = (float*)d_out;

    float *qp, *kp, *vp, *ap;
    cudaGetSymbolAddress((void**)&qp, g_Q);
    cudaGetSymbolAddress((void**)&kp, g_K);
    cudaGetSymbolAddress((void**)&vp, g_V);
    cudaGetSymbolAddress((void**)&ap, g_attn);

    __half *xh, *xl, *wqh, *wql, *wkh, *wkl, *wvh, *wvl, *woh, *wol, *ah, *al;
    cudaGetSymbolAddress((void**)&xh,  g_xh);  cudaGetSymbolAddress((void**)&xl,  g_xl);
    cudaGetSymbolAddress((void**)&wqh, g_wqh); cudaGetSymbolAddress((void**)&wql, g_wql);
    cudaGetSymbolAddress((void**)&wkh, g_wkh); cudaGetSymbolAddress((void**)&wkl, g_wkl);
    cudaGetSymbolAddress((void**)&wvh, g_wvh); cudaGetSymbolAddress((void**)&wvl, g_wvl);
    cudaGetSymbolAddress((void**)&woh, g_woh); cudaGetSymbolAddress((void**)&wol, g_wol);
    cudaGetSymbolAddress((void**)&ah,  g_ah);  cudaGetSymbolAddress((void**)&al,  g_al);

    cudaFuncSetAttribute((const void*)hgemm_split,
                         cudaFuncAttributeMaxDynamicSharedMemorySize, HGEMM_SMEM);
    cudaFuncSetAttribute((const void*)flash_kernel,
                         cudaFuncAttributeMaxDynamicSharedMemorySize, FLASH_SMEM);

    const int NX = S_LEN * D_MODEL;          // 8.4M
    const int NW = D_MODEL * D_MODEL;        // 16.8M
    const int NKW = NKV * HDIM * D_MODEL;    // 4.2M

    split_kernel<<<(NX  + 255) / 256, 256>>>(x,  xh,  xl,  NX);
    split_kernel<<<(NW  + 255) / 256, 256>>>(wq, wqh, wql, NW);
    split_kernel<<<(NKW + 255) / 256, 256>>>(wk, wkh, wkl, NKW);
    split_kernel<<<(NKW + 255) / 256, 256>>>(wv, wvh, wvl, NKW);
    split_kernel<<<(NW  + 255) / 256, 256>>>(wo, woh, wol, NW);

    // QKV projections (tensor cores, split-fp16)
    hgemm_split<<<dim3(32, 16), 256, HGEMM_SMEM>>>(xh, xl, wqh, wql, qp,
                                                   S_LEN, NH * HDIM, D_MODEL);
    hgemm_split<<<dim3(8, 16), 256, HGEMM_SMEM>>>(xh, xl, wkh, wkl, kp,
                                                  S_LEN, NKV * HDIM, D_MODEL);
    hgemm_split<<<dim3(8, 16), 256, HGEMM_SMEM>>>(xh, xl, wvh, wvl, vp,
                                                  S_LEN, NKV * HDIM, D_MODEL);

    // RoPE
    rope_kernel<<<(S_LEN * NH * 64 + 255) / 256, 256>>>(qp, fc, fs, NH);
    rope_kernel<<<(S_LEN * NKV * 64 + 255) / 256, 256>>>(kp, fc, fs, NKV);

    // Flash attention (fp32)
    flash_kernel<<<dim3(32, 32), 256, FLASH_SMEM>>>();

    // Output projection
    split_kernel<<<(NX + 255) / 256, 256>>>(ap, ah, al, NX);
    hgemm_split<<<dim3(32, 16), 256, HGEMM_SMEM>>>(ah, al, woh, wol, out,
                                                   S_LEN, D_MODEL, D_MODEL);
}

// round 4
// speedup vs baseline: 3.0237x; 1.6028x over previous
#include <cuda_runtime.h>
#include <cuda_fp16.h>
#include <math.h>
#include <stdint.h>

#define S_LEN   2048
#define D_MODEL 4096
#define NH      32
#define NKV     8
#define HDIM    128
#define KV_D    (NKV * HDIM)           // 1024
#define ATT_SCALE 0.08838834764831843f // 128^-0.5

// ---------------- static scratch (allocation forbidden) --------------------
__device__ float g_Q[S_LEN * D_MODEL];
__device__ float g_K[S_LEN * KV_D];
__device__ float g_V[S_LEN * KV_D];
__device__ float g_attn[S_LEN * D_MODEL];

// fp16 split buffers for GEMMs
__device__ __half g_xh[S_LEN * D_MODEL],      g_xl[S_LEN * D_MODEL];
__device__ __half g_wqh[D_MODEL * D_MODEL],   g_wql[D_MODEL * D_MODEL];
__device__ __half g_wkh[KV_D * D_MODEL],      g_wkl[KV_D * D_MODEL];
__device__ __half g_wvh[KV_D * D_MODEL],      g_wvl[KV_D * D_MODEL];
__device__ __half g_woh[D_MODEL * D_MODEL],   g_wol[D_MODEL * D_MODEL];
__device__ __half g_ah[S_LEN * D_MODEL],      g_al[S_LEN * D_MODEL];

// fp16 split buffers for flash attention
__device__ __half g_Qfh[S_LEN * D_MODEL], g_Qfl[S_LEN * D_MODEL];  // pre-scaled
__device__ __half g_Kfh[S_LEN * KV_D],    g_Kfl[S_LEN * KV_D];
__device__ __half g_Vth[KV_D * S_LEN],    g_Vtl[KV_D * S_LEN];     // [kvh*128+d][s]

// ---------------------------------------------------------------------------
__device__ __forceinline__ void cp16(uint32_t dst, const void* src) {
    asm volatile("cp.async.cg.shared.global [%0], [%1], 16;\n" :: "r"(dst), "l"(src));
}
#define LDSM4(R0, R1, R2, R3, ADDR)                                          \
    asm volatile("ldmatrix.sync.aligned.m8n8.x4.shared.b16 {%0,%1,%2,%3},[%4];" \
                 : "=r"(R0), "=r"(R1), "=r"(R2), "=r"(R3) : "r"(ADDR))
#define MMA16816(C, A, B0, B1)                                               \
    asm volatile("mma.sync.aligned.m16n8k16.row.col.f32.f16.f16.f32 "        \
                 "{%0,%1,%2,%3},{%4,%5,%6,%7},{%8,%9},{%0,%1,%2,%3};"        \
                 : "+f"((C)[0]), "+f"((C)[1]), "+f"((C)[2]), "+f"((C)[3])    \
                 : "r"((A)[0]), "r"((A)[1]), "r"((A)[2]), "r"((A)[3]),       \
                   "r"(B0), "r"(B1))

// ---------------------------------------------------------------------------
// split fp32*scale -> fp16 hi + fp16 lo
// ---------------------------------------------------------------------------
__global__ void split_scale_h(const float* __restrict__ in,
                              __half* __restrict__ hi, __half* __restrict__ lo,
                              int n, float scale) {
    int i = blockIdx.x * blockDim.x + threadIdx.x;
    if (i >= n) return;
    float a = in[i] * scale;
    __half h = __float2half_rn(a);
    hi[i] = h;
    lo[i] = __float2half_rn(a - __half2float(h));
}

// ---------------------------------------------------------------------------
// transpose + split V: g_V[s][kvh*128+d] fp32 -> Vt[kvh*128+d][s] fp16 hi/lo
// ---------------------------------------------------------------------------
__global__ void transpose_split_v(const float* __restrict__ V,
                                  __half* __restrict__ Vth,
                                  __half* __restrict__ Vtl) {
    __shared__ float tile[32][33];
    const int s0 = blockIdx.x * 32, d0 = blockIdx.y * 32;
    const int tx = threadIdx.x, ty = threadIdx.y;  // 32 x 8
#pragma unroll
    for (int i = 0; i < 4; i++)
        tile[ty + 8 * i][tx] = V[(size_t)(s0 + ty + 8 * i) * KV_D + d0 + tx];
    __syncthreads();
#pragma unroll
    for (int i = 0; i < 4; i++) {
        int d = d0 + ty + 8 * i, s = s0 + tx;
        float v = tile[tx][ty + 8 * i];
        __half h = __float2half_rn(v);
        Vth[(size_t)d * S_LEN + s] = h;
        Vtl[(size_t)d * S_LEN + s] = __float2half_rn(v - __half2float(h));
    }
}

// ---------------------------------------------------------------------------
// HGEMM with fp16 2-term split (unchanged from R2, proven)
// ---------------------------------------------------------------------------
#define HGEMM_SMEM 65536

__global__ __launch_bounds__(256, 1)
void hgemm_split(const __half* __restrict__ Ah, const __half* __restrict__ Al,
                 const __half* __restrict__ Bh, const __half* __restrict__ Bl,
                 float* __restrict__ C, int M, int N, int K) {
    extern __shared__ __half smh[];
    const uint32_t sbase = (uint32_t)__cvta_generic_to_shared(smh);

    const int t    = threadIdx.x;
    const int m0   = blockIdx.y * 128;
    const int n0   = blockIdx.x * 128;
    const int warp = t >> 5;
    const int lane = t & 31;
    const int wm   = (warp >> 1) * 32;
    const int wn   = (warp & 1) * 64;

    const int a_mloc = lane & 15;
    const int a_gsel = lane >> 4;
    const int b_nloc = (lane & 7) + ((lane & 16) >> 1);
    const int b_gsel = (lane >> 3) & 1;

    float acc[2][8][4];
#pragma unroll
    for (int mt = 0; mt < 2; mt++)
#pragma unroll
        for (int nt = 0; nt < 8; nt++)
#pragma unroll
            for (int r = 0; r < 4; r++) acc[mt][nt][r] = 0.f;

    auto issue = [&](int k0, int buf) {
        uint32_t abase = sbase + buf * 32768;
        uint32_t bbase = abase + 16384;
#pragma unroll
        for (int i = 0; i < 4; i++) {
            int ga = t + i * 256;
            int m = ga >> 3, sg = ga & 7;
            const __half* src = (sg < 4 ? Ah : Al)
                              + (size_t)(m0 + m) * K + k0 + (sg & 3) * 8;
            cp16(abase + m * 128 + ((sg ^ (m & 7)) << 4), src);
        }
#pragma unroll
        for (int i = 0; i < 4; i++) {
            int ga = t + i * 256;
            int n = ga >> 3, sg = ga & 7;
            const __half* src = (sg < 4 ? Bh : Bl)
                              + (size_t)(n0 + n) * K + k0 + (sg & 3) * 8;
            cp16(bbase + n * 128 + ((sg ^ (n & 7)) << 4), src);
        }
    };

    const int NIT = K >> 5;
    issue(0, 0);
    asm volatile("cp.async.commit_group;");

    for (int it = 0; it < NIT; it++) {
        if (it + 1 < NIT) {
            issue((it + 1) << 5, (it + 1) & 1);
            asm volatile("cp.async.commit_group;");
            asm volatile("cp.async.wait_group 1;");
        } else {
            asm volatile("cp.async.wait_group 0;");
        }
        __syncthreads();

        const int buf = it & 1;
        const uint32_t abase = sbase + buf * 32768;
        const uint32_t bbase = abase + 16384;

#pragma unroll
        for (int c = 0; c < 2; c++) {
            uint32_t ah[2][4], al[2][4], bb[4][4];
#pragma unroll
            for (int mt = 0; mt < 2; mt++) {
                int m = wm + mt * 16 + a_mloc;
                int sg = 2 * c + a_gsel;
                LDSM4(ah[mt][0], ah[mt][1], ah[mt][2], ah[mt][3],
                      abase + m * 128 + ((sg ^ (m & 7)) << 4));
            }
#pragma unroll
            for (int p = 0; p < 4; p++) {
                int n = wn + p * 16 + b_nloc;
                int sg = 2 * c + b_gsel;
                LDSM4(bb[p][0], bb[p][1], bb[p][2], bb[p][3],
                      bbase + n * 128 + ((sg ^ (n & 7)) << 4));
            }
#pragma unroll
            for (int mt = 0; mt < 2; mt++)
#pragma unroll
                for (int p = 0; p < 4; p++) {
                    MMA16816(acc[mt][2 * p],     ah[mt], bb[p][0], bb[p][1]);
                    MMA16816(acc[mt][2 * p + 1], ah[mt], bb[p][2], bb[p][3]);
                }
#pragma unroll
            for (int mt = 0; mt < 2; mt++) {
                int m = wm + mt * 16 + a_mloc;
                int sg = 4 + 2 * c + a_gsel;
                LDSM4(al[mt][0], al[mt][1], al[mt][2], al[mt][3],
                      abase + m * 128 + ((sg ^ (m & 7)) << 4));
            }
#pragma unroll
            for (int mt = 0; mt < 2; mt++)
#pragma unroll
                for (int p = 0; p < 4; p++) {
                    MMA16816(acc[mt][2 * p],     al[mt], bb[p][0], bb[p][1]);
                    MMA16816(acc[mt][2 * p + 1], al[mt], bb[p][2], bb[p][3]);
                }
#pragma unroll
            for (int p = 0; p < 4; p++) {
                int n = wn + p * 16 + b_nloc;
                int sg = 4 + 2 * c + b_gsel;
                LDSM4(bb[p][0], bb[p][1], bb[p][2], bb[p][3],
                      bbase + n * 128 + ((sg ^ (n & 7)) << 4));
            }
#pragma unroll
            for (int mt = 0; mt < 2; mt++)
#pragma unroll
                for (int p = 0; p < 4; p++) {
                    MMA16816(acc[mt][2 * p],     ah[mt], bb[p][0], bb[p][1]);
                    MMA16816(acc[mt][2 * p + 1], ah[mt], bb[p][2], bb[p][3]);
                }
        }
        __syncthreads();
    }

#pragma unroll
    for (int mt = 0; mt < 2; mt++) {
        int r = m0 + wm + mt * 16 + (lane >> 2);
#pragma unroll
        for (int nt = 0; nt < 8; nt++) {
            int cc = n0 + wn + nt * 8 + (lane & 3) * 2;
            float* p0 = C + (size_t)r * N + cc;
            p0[0] = acc[mt][nt][0];
            p0[1] = acc[mt][nt][1];
            float* p1 = p0 + 8 * N;
            p1[0] = acc[mt][nt][2];
            p1[1] = acc[mt][nt][3];
        }
    }
}

// ---------------------------------------------------------------------------
// RoPE (unchanged)
// ---------------------------------------------------------------------------
__global__ void rope_kernel(float* __restrict__ t, const float* __restrict__ cosw,
                            const float* __restrict__ sinw, int nheads) {
    int idx = blockIdx.x * blockDim.x + threadIdx.x;
    int total = S_LEN * nheads * (HDIM / 2);
    if (idx >= total) return;
    int i = idx & 63;
    int h = (idx >> 6) % nheads;
    int s = idx / (64 * nheads);
    float c  = cosw[s * 64 + i];
    float sn = sinw[s * 64 + i];
    float* p = t + (size_t)s * nheads * HDIM + h * HDIM + 2 * i;
    float t0 = p[0], t1 = p[1];
    p[0] = t0 * c - t1 * sn;
    p[1] = t0 * sn + t1 * c;
}

// ---------------------------------------------------------------------------
// Flash attention on tensor cores (split-fp16 mma.sync).
// CTA = (64-row q tile, head); 128 threads = 4 warps, 16 q rows per warp.
// smem: Qh,Ql [64][128h] | Kh,Kl [64][128h] | Vth,Vtl [128][64h]
// ---------------------------------------------------------------------------
#define FQ_OFF  0
#define FK_OFF  32768
#define FV_OFF  65536
#define FLASH_TC_SMEM 98304

__device__ __forceinline__ uint32_t pack_split(float a, float b, uint32_t& lo) {
    __half ah = __float2half_rn(a), bh = __float2half_rn(b);
    __half al = __float2half_rn(a - __half2float(ah));
    __half bl = __float2half_rn(b - __half2float(bh));
    __half2 h2 = __halves2half2(ah, bh);
    __half2 l2 = __halves2half2(al, bl);
    lo = *(uint32_t*)&l2;
    return *(uint32_t*)&h2;
}

__global__ __launch_bounds__(128, 1)
void flash_tc(const __half* __restrict__ Qh, const __half* __restrict__ Ql,
              const __half* __restrict__ Kh, const __half* __restrict__ Kl,
              const __half* __restrict__ Vth, const __half* __restrict__ Vtl) {
    extern __shared__ char smc[];
    const uint32_t sb = (uint32_t)__cvta_generic_to_shared(smc);
    const int t    = threadIdx.x;
    const int lane = t & 31;
    const int warp = t >> 5;
    const int qt   = (int)gridDim.x - 1 - (int)blockIdx.x;  // longest first
    const int h    = blockIdx.y;
    const int kh   = h >> 2;
    const int q0   = qt * 64;

    const int a_ml = lane & 15;
    const int a_gs = lane >> 4;
    const int b_nl = (lane & 7) + ((lane & 16) >> 1);
    const int b_gs = (lane >> 3) & 1;

    // ---- Q tile load (once): 2048 granules, 16/thread ----
#pragma unroll
    for (int i = 0; i < 16; i++) {
        int g = t + i * 128;
        int half = g >> 10, gg = g & 1023;
        int r = gg >> 4, c = gg & 15;
        const __half* src = (half ? Ql : Qh)
                          + (size_t)(q0 + r) * D_MODEL + h * HDIM + c * 8;
        cp16(sb + FQ_OFF + half * 16384 + r * 256 + ((c ^ (r & 7)) << 4), src);
    }
    asm volatile("cp.async.commit_group;");

    float o[16][4];
#pragma unroll
    for (int nt = 0; nt < 16; nt++)
#pragma unroll
        for (int j = 0; j < 4; j++) o[nt][j] = 0.f;
    float m0r = -1e30f, m1r = -1e30f, l0 = 0.f, l1 = 0.f;

    for (int kt = 0; kt <= qt; kt++) {
        const int k0 = kt * 64;
        __syncthreads();  // previous iter's K/V reads done
        // K tile: 2048 granules
#pragma unroll
        for (int i = 0; i < 16; i++) {
            int g = t + i * 128;
            int half = g >> 10, gg = g & 1023;
            int r = gg >> 4, c = gg & 15;
            const __half* src = (half ? Kl : Kh)
                              + (size_t)(k0 + r) * KV_D + kh * HDIM + c * 8;
            cp16(sb + FK_OFF + half * 16384 + r * 256 + ((c ^ (r & 7)) << 4), src);
        }
        // Vt tile: 2048 granules
#pragma unroll
        for (int i = 0; i < 16; i++) {
            int g = t + i * 128;
            int half = g >> 10, gg = g & 1023;
            int r = gg >> 3, c = gg & 7;
            const __half* src = (half ? Vtl : Vth)
                              + (size_t)(kh * HDIM + r) * S_LEN + k0 + c * 8;
            cp16(sb + FV_OFF + half * 16384 + r * 128 + ((c ^ (r & 7)) << 4), src);
        }
        asm volatile("cp.async.commit_group;");
        asm volatile("cp.async.wait_group 0;");
        __syncthreads();

        // ---- S = Qs @ K^T (split: QhKh + QhKl + QlKh) ----
        float sacc[8][4];
#pragma unroll
        for (int nt = 0; nt < 8; nt++)
#pragma unroll
            for (int j = 0; j < 4; j++) sacc[nt][j] = 0.f;

#pragma unroll
        for (int kc = 0; kc < 8; kc++) {
            uint32_t aqh[4], aql[4];
            {
                int r = warp * 16 + a_ml;
                int cf = 2 * kc + a_gs;
                uint32_t qa = sb + FQ_OFF + r * 256 + ((cf ^ (r & 7)) << 4);
                LDSM4(aqh[0], aqh[1], aqh[2], aqh[3], qa);
                LDSM4(aql[0], aql[1], aql[2], aql[3], qa + 16384);
            }
#pragma unroll
            for (int p = 0; p < 4; p++) {
                int n = p * 16 + b_nl;
                int cf = 2 * kc + b_gs;
                uint32_t ka = sb + FK_OFF + n * 256 + ((cf ^ (n & 7)) << 4);
                uint32_t bh[4], bl[4];
                LDSM4(bh[0], bh[1], bh[2], bh[3], ka);
                LDSM4(bl[0], bl[1], bl[2], bl[3], ka + 16384);
                MMA16816(sacc[2 * p],     aqh, bh[0], bh[1]);
                MMA16816(sacc[2 * p + 1], aqh, bh[2], bh[3]);
                MMA16816(sacc[2 * p],     aqh, bl[0], bl[1]);
                MMA16816(sacc[2 * p + 1], aqh, bl[2], bl[3]);
                MMA16816(sacc[2 * p],     aql, bh[0], bh[1]);
                MMA16816(sacc[2 * p + 1], aql, bh[2], bh[3]);
            }
        }

        // ---- causal mask on diagonal tile ----
        if (kt == qt) {
            int rg0 = q0 + warp * 16 + (lane >> 2);
#pragma unroll
            for (int nt = 0; nt < 8; nt++) {
                int cg = k0 + nt * 8 + (lane & 3) * 2;
                if (cg     > rg0)     sacc[nt][0] += -1e9f;
                if (cg + 1 > rg0)     sacc[nt][1] += -1e9f;
                if (cg     > rg0 + 8) sacc[nt][2] += -1e9f;
                if (cg + 1 > rg0 + 8) sacc[nt][3] += -1e9f;
            }
        }

        // ---- online softmax (fp32 in registers) ----
        float rmax0 = -1e30f, rmax1 = -1e30f;
#pragma unroll
        for (int nt = 0; nt < 8; nt++) {
            rmax0 = fmaxf(rmax0, fmaxf(sacc[nt][0], sacc[nt][1]));
            rmax1 = fmaxf(rmax1, fmaxf(sacc[nt][2], sacc[nt][3]));
        }
#pragma unroll
        for (int off = 1; off < 4; off <<= 1) {
            rmax0 = fmaxf(rmax0, __shfl_xor_sync(0xffffffffu, rmax0, off));
            rmax1 = fmaxf(rmax1, __shfl_xor_sync(0xffffffffu, rmax1, off));
        }
        float mn0 = fmaxf(m0r, rmax0), mn1 = fmaxf(m1r, rmax1);
        float al0 = __expf(m0r - mn0), al1 = __expf(m1r - mn1);
        m0r = mn0; m1r = mn1;

        float rs0 = 0.f, rs1 = 0.f;
#pragma unroll
        for (int nt = 0; nt < 8; nt++) {
            sacc[nt][0] = __expf(sacc[nt][0] - mn0);
            sacc[nt][1] = __expf(sacc[nt][1] - mn0);
            sacc[nt][2] = __expf(sacc[nt][2] - mn1);
            sacc[nt][3] = __expf(sacc[nt][3] - mn1);
            rs0 += sacc[nt][0] + sacc[nt][1];
            rs1 += sacc[nt][2] + sacc[nt][3];
        }
#pragma unroll
        for (int off = 1; off < 4; off <<= 1) {
            rs0 += __shfl_xor_sync(0xffffffffu, rs0, off);
            rs1 += __shfl_xor_sync(0xffffffffu, rs1, off);
        }
        l0 = l0 * al0 + rs0;
        l1 = l1 * al1 + rs1;
#pragma unroll
        for (int nt = 0; nt < 16; nt++) {
            o[nt][0] *= al0; o[nt][1] *= al0;
            o[nt][2] *= al1; o[nt][3] *= al1;
        }

        // ---- O += P @ V (split: PhVh + PhVl + PlVh) ----
#pragma unroll
        for (int kc = 0; kc < 4; kc++) {
            uint32_t ph[4], pl[4];
            ph[0] = pack_split(sacc[2 * kc][0],     sacc[2 * kc][1],     pl[0]);
            ph[1] = pack_split(sacc[2 * kc][2],     sacc[2 * kc][3],     pl[1]);
            ph[2] = pack_split(sacc[2 * kc + 1][0], sacc[2 * kc + 1][1], pl[2]);
            ph[3] = pack_split(sacc[2 * kc + 1][2], sacc[2 * kc + 1][3], pl[3]);
#pragma unroll
            for (int p = 0; p < 8; p++) {
                int n = p * 16 + b_nl;
                int cf = 2 * kc + b_gs;
                uint32_t va = sb + FV_OFF + n * 128 + ((cf ^ (n & 7)) << 4);
                uint32_t bh[4], bl[4];
                LDSM4(bh[0], bh[1], bh[2], bh[3], va);
                LDSM4(bl[0], bl[1], bl[2], bl[3], va + 16384);
                MMA16816(o[2 * p],     ph, bh[0], bh[1]);
                MMA16816(o[2 * p + 1], ph, bh[2], bh[3]);
                MMA16816(o[2 * p],     ph, bl[0], bl[1]);
                MMA16816(o[2 * p + 1], ph, bl[2], bl[3]);
                MMA16816(o[2 * p],     pl, bh[0], bh[1]);
                MMA16816(o[2 * p + 1], pl, bh[2], bh[3]);
            }
        }
    }

    // ---- epilogue ----
    float inv0 = 1.f / l0, inv1 = 1.f / l1;
    int rg0 = q0 + warp * 16 + (lane >> 2);
#pragma unroll
    for (int nt = 0; nt < 16; nt++) {
        int col = h * HDIM + nt * 8 + (lane & 3) * 2;
        float* p0 = g_attn + (size_t)rg0 * D_MODEL + col;
        p0[0] = o[nt][0] * inv0;
        p0[1] = o[nt][1] * inv0;
        float* p1 = p0 + 8 * D_MODEL;
        p1[0] = o[nt][2] * inv1;
        p1[1] = o[nt][3] * inv1;
    }
}

// ---------------------------------------------------------------------------
extern "C" void kernel_launch(void* const* d_in, const int* in_sizes, int n_in,
                              void* d_out, int out_size) {
    const float* x  = (const float*)d_in[0];
    const float* fc = (const float*)d_in[1];
    const float* fs = (const float*)d_in[2];
    const float* wq = (const float*)d_in[4];
    const float* wk = (const float*)d_in[5];
    const float* wv = (const float*)d_in[6];
    const float* wo = (const float*)d_in[7];
    float* out = (float*)d_out;

    float *qp, *kp, *vp, *ap;
    cudaGetSymbolAddress((void**)&qp, g_Q);
    cudaGetSymbolAddress((void**)&kp, g_K);
    cudaGetSymbolAddress((void**)&vp, g_V);
    cudaGetSymbolAddress((void**)&ap, g_attn);

    __half *xh, *xl, *wqh, *wql, *wkh, *wkl, *wvh, *wvl, *woh, *wol, *ah, *al;
    __half *qfh, *qfl, *kfh, *kfl, *vth, *vtl;
    cudaGetSymbolAddress((void**)&xh,  g_xh);  cudaGetSymbolAddress((void**)&xl,  g_xl);
    cudaGetSymbolAddress((void**)&wqh, g_wqh); cudaGetSymbolAddress((void**)&wql, g_wql);
    cudaGetSymbolAddress((void**)&wkh, g_wkh); cudaGetSymbolAddress((void**)&wkl, g_wkl);
    cudaGetSymbolAddress((void**)&wvh, g_wvh); cudaGetSymbolAddress((void**)&wvl, g_wvl);
    cudaGetSymbolAddress((void**)&woh, g_woh); cudaGetSymbolAddress((void**)&wol, g_wol);
    cudaGetSymbolAddress((void**)&ah,  g_ah);  cudaGetSymbolAddress((void**)&al,  g_al);
    cudaGetSymbolAddress((void**)&qfh, g_Qfh); cudaGetSymbolAddress((void**)&qfl, g_Qfl);
    cudaGetSymbolAddress((void**)&kfh, g_Kfh); cudaGetSymbolAddress((void**)&kfl, g_Kfl);
    cudaGetSymbolAddress((void**)&vth, g_Vth); cudaGetSymbolAddress((void**)&vtl, g_Vtl);

    cudaFuncSetAttribute((const void*)hgemm_split,
                         cudaFuncAttributeMaxDynamicSharedMemorySize, HGEMM_SMEM);
    cudaFuncSetAttribute((const void*)flash_tc,
                         cudaFuncAttributeMaxDynamicSharedMemorySize, FLASH_TC_SMEM);

    const int NX  = S_LEN * D_MODEL;
    const int NW  = D_MODEL * D_MODEL;
    const int NKW = KV_D * D_MODEL;
    const int NKX = S_LEN * KV_D;

    split_scale_h<<<(NX  + 255) / 256, 256>>>(x,  xh,  xl,  NX,  1.f);
    split_scale_h<<<(NW  + 255) / 256, 256>>>(wq, wqh, wql, NW,  1.f);
    split_scale_h<<<(NKW + 255) / 256, 256>>>(wk, wkh, wkl, NKW, 1.f);
    split_scale_h<<<(NKW + 255) / 256, 256>>>(wv, wvh, wvl, NKW, 1.f);
    split_scale_h<<<(NW  + 255) / 256, 256>>>(wo, woh, wol, NW,  1.f);

    // QKV projections
    hgemm_split<<<dim3(32, 16), 256, HGEMM_SMEM>>>(xh, xl, wqh, wql, qp,
                                                   S_LEN, NH * HDIM, D_MODEL);
    hgemm_split<<<dim3(8, 16), 256, HGEMM_SMEM>>>(xh, xl, wkh, wkl, kp,
                                                  S_LEN, KV_D, D_MODEL);
    hgemm_split<<<dim3(8, 16), 256, HGEMM_SMEM>>>(xh, xl, wvh, wvl, vp,
                                                  S_LEN, KV_D, D_MODEL);

    // RoPE (fp32 in place)
    rope_kernel<<<(S_LEN * NH * 64 + 255) / 256, 256>>>(qp, fc, fs, NH);
    rope_kernel<<<(S_LEN * NKV * 64 + 255) / 256, 256>>>(kp, fc, fs, NKV);

    // fp16 splits for flash
    split_scale_h<<<(NX  + 255) / 256, 256>>>(qp, qfh, qfl, NX,  ATT_SCALE);
    split_scale_h<<<(NKX + 255) / 256, 256>>>(kp, kfh, kfl, NKX, 1.f);
    transpose_split_v<<<dim3(S_LEN / 32, KV_D / 32), dim3(32, 8)>>>(vp, vth, vtl);

    // Flash attention on tensor cores
    flash_tc<<<dim3(32, 32), 128, FLASH_TC_SMEM>>>(qfh, qfl, kfh, kfl, vth, vtl);

    // Output projection
    split_scale_h<<<(NX + 255) / 256, 256>>>(ap, ah, al, NX, 1.f);
    hgemm_split<<<dim3(32, 16), 256, HGEMM_SMEM>>>(ah, al, woh, wol, out,
                                                   S_LEN, D_MODEL, D_MODEL);
}

// round 7
// speedup vs baseline: 3.2630x; 1.0791x over previous
#include <cuda_runtime.h>
#include <cuda_fp16.h>
#include <math.h>
#include <stdint.h>

#define S_LEN   2048
#define D_MODEL 4096
#define NH      32
#define NKV     8
#define HDIM    128
#define KV_D    (NKV * HDIM)           // 1024
#define ATT_SCALE 0.08838834764831843f // 128^-0.5

// ---------------- static scratch (allocation forbidden) --------------------
__device__ float g_V[S_LEN * KV_D];

// fp16 split buffers
__device__ __half g_xh[S_LEN * D_MODEL],      g_xl[S_LEN * D_MODEL];
__device__ __half g_wqh[D_MODEL * D_MODEL],   g_wql[D_MODEL * D_MODEL];
__device__ __half g_wkh[KV_D * D_MODEL],      g_wkl[KV_D * D_MODEL];
__device__ __half g_wvh[KV_D * D_MODEL],      g_wvl[KV_D * D_MODEL];
__device__ __half g_woh[D_MODEL * D_MODEL],   g_wol[D_MODEL * D_MODEL];
__device__ __half g_ah[S_LEN * D_MODEL],      g_al[S_LEN * D_MODEL];

__device__ __half g_Qfh[S_LEN * D_MODEL], g_Qfl[S_LEN * D_MODEL];  // pre-scaled, rope'd
__device__ __half g_Kfh[S_LEN * KV_D],    g_Kfl[S_LEN * KV_D];     // rope'd
__device__ __half g_Vth[KV_D * S_LEN],    g_Vtl[KV_D * S_LEN];     // [kvh*128+d][s]

// ---------------------------------------------------------------------------
__device__ __forceinline__ void cp16(uint32_t dst, const void* src) {
    asm volatile("cp.async.cg.shared.global [%0], [%1], 16;\n" :: "r"(dst), "l"(src));
}
#define LDSM4(R0, R1, R2, R3, ADDR)                                          \
    asm volatile("ldmatrix.sync.aligned.m8n8.x4.shared.b16 {%0,%1,%2,%3},[%4];" \
                 : "=r"(R0), "=r"(R1), "=r"(R2), "=r"(R3) : "r"(ADDR))
#define MMA16816(C, A, B0, B1)                                               \
    asm volatile("mma.sync.aligned.m16n8k16.row.col.f32.f16.f16.f32 "        \
                 "{%0,%1,%2,%3},{%4,%5,%6,%7},{%8,%9},{%0,%1,%2,%3};"        \
                 : "+f"((C)[0]), "+f"((C)[1]), "+f"((C)[2]), "+f"((C)[3])    \
                 : "r"((A)[0]), "r"((A)[1]), "r"((A)[2]), "r"((A)[3]),       \
                   "r"(B0), "r"(B1))

__device__ __forceinline__ __half2 split_pair(float a, float b, __half2& lo) {
    __half ah = __float2half_rn(a), bh = __float2half_rn(b);
    lo = __halves2half2(__float2half_rn(a - __half2float(ah)),
                        __float2half_rn(b - __half2float(bh)));
    return __halves2half2(ah, bh);
}

// ---------------------------------------------------------------------------
// split fp32 -> fp16 hi + fp16 lo
// ---------------------------------------------------------------------------
__global__ void split_h(const float* __restrict__ in,
                        __half* __restrict__ hi, __half* __restrict__ lo, int n) {
    int i = blockIdx.x * blockDim.x + threadIdx.x;
    if (i >= n) return;
    float a = in[i];
    __half h = __float2half_rn(a);
    hi[i] = h;
    lo[i] = __float2half_rn(a - __half2float(h));
}

// ---------------------------------------------------------------------------
// transpose + split V
// ---------------------------------------------------------------------------
__global__ void transpose_split_v(const float* __restrict__ V,
                                  __half* __restrict__ Vth,
                                  __half* __restrict__ Vtl) {
    __shared__ float tile[32][33];
    const int s0 = blockIdx.x * 32, d0 = blockIdx.y * 32;
    const int tx = threadIdx.x, ty = threadIdx.y;
#pragma unroll
    for (int i = 0; i < 4; i++)
        tile[ty + 8 * i][tx] = V[(size_t)(s0 + ty + 8 * i) * KV_D + d0 + tx];
    __syncthreads();
#pragma unroll
    for (int i = 0; i < 4; i++) {
        int d = d0 + ty + 8 * i, s = s0 + tx;
        float v = tile[tx][ty + 8 * i];
        __half h = __float2half_rn(v);
        Vth[(size_t)d * S_LEN + s] = h;
        Vtl[(size_t)d * S_LEN + s] = __float2half_rn(v - __half2float(h));
    }
}

// ---------------------------------------------------------------------------
// HGEMM split-fp16.  MODE 0: fp32 C out.  MODE 1: rope+scale+split fp16 out.
// 128x128 tile, k32, 3-stage cp.async ring, 256 threads, 2 CTAs/SM.
// ---------------------------------------------------------------------------
#define HGEMM_SMEM (3 * 32768)

template<int MODE>
__global__ __launch_bounds__(256, 2)
void hgemm_split(const __half* __restrict__ Ah, const __half* __restrict__ Al,
                 const __half* __restrict__ Bh, const __half* __restrict__ Bl,
                 float* __restrict__ C,
                 __half* __restrict__ Hi, __half* __restrict__ Lo,
                 const float* __restrict__ cosw, const float* __restrict__ sinw,
                 float scale, int M, int N, int K) {
    extern __shared__ __half smh[];
    const uint32_t sbase = (uint32_t)__cvta_generic_to_shared(smh);

    const int t    = threadIdx.x;
    const int m0   = blockIdx.y * 128;
    const int n0   = blockIdx.x * 128;
    const int warp = t >> 5;
    const int lane = t & 31;
    const int wm   = (warp >> 1) * 32;
    const int wn   = (warp & 1) * 64;

    const int a_mloc = lane & 15;
    const int a_gsel = lane >> 4;
    const int b_nloc = (lane & 7) + ((lane & 16) >> 1);
    const int b_gsel = (lane >> 3) & 1;

    float acc[2][8][4];
#pragma unroll
    for (int mt = 0; mt < 2; mt++)
#pragma unroll
        for (int nt = 0; nt < 8; nt++)
#pragma unroll
            for (int r = 0; r < 4; r++) acc[mt][nt][r] = 0.f;

    auto issue = [&](int k0, int buf) {
        uint32_t abase = sbase + buf * 32768;
        uint32_t bbase = abase + 16384;
#pragma unroll
        for (int i = 0; i < 4; i++) {
            int ga = t + i * 256;
            int m = ga >> 3, sg = ga & 7;
            const __half* src = (sg < 4 ? Ah : Al)
                              + (size_t)(m0 + m) * K + k0 + (sg & 3) * 8;
            cp16(abase + m * 128 + ((sg ^ (m & 7)) << 4), src);
        }
#pragma unroll
        for (int i = 0; i < 4; i++) {
            int ga = t + i * 256;
            int n = ga >> 3, sg = ga & 7;
            const __half* src = (sg < 4 ? Bh : Bl)
                              + (size_t)(n0 + n) * K + k0 + (sg & 3) * 8;
            cp16(bbase + n * 128 + ((sg ^ (n & 7)) << 4), src);
        }
    };

    const int NIT = K >> 5;
    issue(0, 0);
    asm volatile("cp.async.commit_group;");
    issue(32, 1);
    asm volatile("cp.async.commit_group;");

    for (int it = 0; it < NIT; it++) {
        if (it + 2 < NIT) {
            issue((it + 2) << 5, (it + 2) % 3);
            asm volatile("cp.async.commit_group;");
            asm volatile("cp.async.wait_group 2;");
        } else if (it + 1 < NIT) {
            asm volatile("cp.async.wait_group 1;");
        } else {
            asm volatile("cp.async.wait_group 0;");
        }
        __syncthreads();

        const uint32_t abase = sbase + (it % 3) * 32768;
        const uint32_t bbase = abase + 16384;

#pragma unroll
        for (int c = 0; c < 2; c++) {
            uint32_t ah[2][4], al[2][4], bb[4][4];
#pragma unroll
            for (int mt = 0; mt < 2; mt++) {
                int m = wm + mt * 16 + a_mloc;
                int sg = 2 * c + a_gsel;
                LDSM4(ah[mt][0], ah[mt][1], ah[mt][2], ah[mt][3],
                      abase + m * 128 + ((sg ^ (m & 7)) << 4));
            }
#pragma unroll
            for (int p = 0; p < 4; p++) {
                int n = wn + p * 16 + b_nloc;
                int sg = 2 * c + b_gsel;
                LDSM4(bb[p][0], bb[p][1], bb[p][2], bb[p][3],
                      bbase + n * 128 + ((sg ^ (n & 7)) << 4));
            }
#pragma unroll
            for (int mt = 0; mt < 2; mt++)
#pragma unroll
                for (int p = 0; p < 4; p++) {
                    MMA16816(acc[mt][2 * p],     ah[mt], bb[p][0], bb[p][1]);
                    MMA16816(acc[mt][2 * p + 1], ah[mt], bb[p][2], bb[p][3]);
                }
#pragma unroll
            for (int mt = 0; mt < 2; mt++) {
                int m = wm + mt * 16 + a_mloc;
                int sg = 4 + 2 * c + a_gsel;
                LDSM4(al[mt][0], al[mt][1], al[mt][2], al[mt][3],
                      abase + m * 128 + ((sg ^ (m & 7)) << 4));
            }
#pragma unroll
            for (int mt = 0; mt < 2; mt++)
#pragma unroll
                for (int p = 0; p < 4; p++) {
                    MMA16816(acc[mt][2 * p],     al[mt], bb[p][0], bb[p][1]);
                    MMA16816(acc[mt][2 * p + 1], al[mt], bb[p][2], bb[p][3]);
                }
#pragma unroll
            for (int p = 0; p < 4; p++) {
                int n = wn + p * 16 + b_nloc;
                int sg = 4 + 2 * c + b_gsel;
                LDSM4(bb[p][0], bb[p][1], bb[p][2], bb[p][3],
                      bbase + n * 128 + ((sg ^ (n & 7)) << 4));
            }
#pragma unroll
            for (int mt = 0; mt < 2; mt++)
#pragma unroll
                for (int p = 0; p < 4; p++) {
                    MMA16816(acc[mt][2 * p],     ah[mt], bb[p][0], bb[p][1]);
                    MMA16816(acc[mt][2 * p + 1], ah[mt], bb[p][2], bb[p][3]);
                }
        }
        __syncthreads();
    }

    // ---- epilogue ----
#pragma unroll
    for (int mt = 0; mt < 2; mt++) {
        int r = m0 + wm + mt * 16 + (lane >> 2);
#pragma unroll
        for (int nt = 0; nt < 8; nt++) {
            int cc = n0 + wn + nt * 8 + (lane & 3) * 2;
            if (MODE == 0) {
                float* p0 = C + (size_t)r * N + cc;
                p0[0] = acc[mt][nt][0];
                p0[1] = acc[mt][nt][1];
                float* p1 = p0 + 8 * N;
                p1[0] = acc[mt][nt][2];
                p1[1] = acc[mt][nt][3];
            } else {
                int i = (cc & 127) >> 1;   // cc even -> rope pair (cc, cc+1)
                {
                    float cw = cosw[r * 64 + i], sw = sinw[r * 64 + i];
                    float t0 = acc[mt][nt][0], t1 = acc[mt][nt][1];
                    float r0 = (t0 * cw - t1 * sw) * scale;
                    float r1 = (t0 * sw + t1 * cw) * scale;
                    __half2 lo2, hi2 = split_pair(r0, r1, lo2);
                    *(__half2*)(Hi + (size_t)r * N + cc) = hi2;
                    *(__half2*)(Lo + (size_t)r * N + cc) = lo2;
                }
                {
                    int r8 = r + 8;
                    float cw = cosw[r8 * 64 + i], sw = sinw[r8 * 64 + i];
                    float t0 = acc[mt][nt][2], t1 = acc[mt][nt][3];
                    float r0 = (t0 * cw - t1 * sw) * scale;
                    float r1 = (t0 * sw + t1 * cw) * scale;
                    __half2 lo2, hi2 = split_pair(r0, r1, lo2);
                    *(__half2*)(Hi + (size_t)r8 * N + cc) = hi2;
                    *(__half2*)(Lo + (size_t)r8 * N + cc) = lo2;
                }
            }
        }
    }
}

// ---------------------------------------------------------------------------
// Flash attention on tensor cores (split-fp16 mma.sync), split-fp16 output.
// ---------------------------------------------------------------------------
#define FQ_OFF  0
#define FK_OFF  32768
#define FV_OFF  65536
#define FLASH_TC_SMEM 98304

__global__ __launch_bounds__(128, 1)
void flash_tc(const __half* __restrict__ Qh, const __half* __restrict__ Ql,
              const __half* __restrict__ Kh, const __half* __restrict__ Kl,
              const __half* __restrict__ Vth, const __half* __restrict__ Vtl,
              __half* __restrict__ Oh, __half* __restrict__ Ol) {
    extern __shared__ char smc[];
    const uint32_t sb = (uint32_t)__cvta_generic_to_shared(smc);
    const int t    = threadIdx.x;
    const int lane = t & 31;
    const int warp = t >> 5;
    const int qt   = (int)gridDim.x - 1 - (int)blockIdx.x;
    const int h    = blockIdx.y;
    const int kh   = h >> 2;
    const int q0   = qt * 64;

    const int a_ml = lane & 15;
    const int a_gs = lane >> 4;
    const int b_nl = (lane & 7) + ((lane & 16) >> 1);
    const int b_gs = (lane >> 3) & 1;

#pragma unroll
    for (int i = 0; i < 16; i++) {
        int g = t + i * 128;
        int half = g >> 10, gg = g & 1023;
        int r = gg >> 4, c = gg & 15;
        const __half* src = (half ? Ql : Qh)
                          + (size_t)(q0 + r) * D_MODEL + h * HDIM + c * 8;
        cp16(sb + FQ_OFF + half * 16384 + r * 256 + ((c ^ (r & 7)) << 4), src);
    }
    asm volatile("cp.async.commit_group;");

    float o[16][4];
#pragma unroll
    for (int nt = 0; nt < 16; nt++)
#pragma unroll
        for (int j = 0; j < 4; j++) o[nt][j] = 0.f;
    float m0r = -1e30f, m1r = -1e30f, l0 = 0.f, l1 = 0.f;

    for (int kt = 0; kt <= qt; kt++) {
        const int k0 = kt * 64;
        __syncthreads();
#pragma unroll
        for (int i = 0; i < 16; i++) {
            int g = t + i * 128;
            int half = g >> 10, gg = g & 1023;
            int r = gg >> 4, c = gg & 15;
            const __half* src = (half ? Kl : Kh)
                              + (size_t)(k0 + r) * KV_D + kh * HDIM + c * 8;
            cp16(sb + FK_OFF + half * 16384 + r * 256 + ((c ^ (r & 7)) << 4), src);
        }
#pragma unroll
        for (int i = 0; i < 16; i++) {
            int g = t + i * 128;
            int half = g >> 10, gg = g & 1023;
            int r = gg >> 3, c = gg & 7;
            const __half* src = (half ? Vtl : Vth)
                              + (size_t)(kh * HDIM + r) * S_LEN + k0 + c * 8;
            cp16(sb + FV_OFF + half * 16384 + r * 128 + ((c ^ (r & 7)) << 4), src);
        }
        asm volatile("cp.async.commit_group;");
        asm volatile("cp.async.wait_group 0;");
        __syncthreads();

        float sacc[8][4];
#pragma unroll
        for (int nt = 0; nt < 8; nt++)
#pragma unroll
            for (int j = 0; j < 4; j++) sacc[nt][j] = 0.f;

#pragma unroll
        for (int kc = 0; kc < 8; kc++) {
            uint32_t aqh[4], aql[4];
            {
                int r = warp * 16 + a_ml;
                int cf = 2 * kc + a_gs;
                uint32_t qa = sb + FQ_OFF + r * 256 + ((cf ^ (r & 7)) << 4);
                LDSM4(aqh[0], aqh[1], aqh[2], aqh[3], qa);
                LDSM4(aql[0], aql[1], aql[2], aql[3], qa + 16384);
            }
#pragma unroll
            for (int p = 0; p < 4; p++) {
                int n = p * 16 + b_nl;
                int cf = 2 * kc + b_gs;
                uint32_t ka = sb + FK_OFF + n * 256 + ((cf ^ (n & 7)) << 4);
                uint32_t bh[4], bl[4];
                LDSM4(bh[0], bh[1], bh[2], bh[3], ka);
                LDSM4(bl[0], bl[1], bl[2], bl[3], ka + 16384);
                MMA16816(sacc[2 * p],     aqh, bh[0], bh[1]);
                MMA16816(sacc[2 * p + 1], aqh, bh[2], bh[3]);
                MMA16816(sacc[2 * p],     aqh, bl[0], bl[1]);
                MMA16816(sacc[2 * p + 1], aqh, bl[2], bl[3]);
                MMA16816(sacc[2 * p],     aql, bh[0], bh[1]);
                MMA16816(sacc[2 * p + 1], aql, bh[2], bh[3]);
            }
        }

        if (kt == qt) {
            int rg0 = q0 + warp * 16 + (lane >> 2);
#pragma unroll
            for (int nt = 0; nt < 8; nt++) {
                int cg = k0 + nt * 8 + (lane & 3) * 2;
                if (cg     > rg0)     sacc[nt][0] += -1e9f;
                if (cg + 1 > rg0)     sacc[nt][1] += -1e9f;
                if (cg     > rg0 + 8) sacc[nt][2] += -1e9f;
                if (cg + 1 > rg0 + 8) sacc[nt][3] += -1e9f;
            }
        }

        float rmax0 = -1e30f, rmax1 = -1e30f;
#pragma unroll
        for (int nt = 0; nt < 8; nt++) {
            rmax0 = fmaxf(rmax0, fmaxf(sacc[nt][0], sacc[nt][1]));
            rmax1 = fmaxf(rmax1, fmaxf(sacc[nt][2], sacc[nt][3]));
        }
#pragma unroll
        for (int off = 1; off < 4; off <<= 1) {
            rmax0 = fmaxf(rmax0, __shfl_xor_sync(0xffffffffu, rmax0, off));
            rmax1 = fmaxf(rmax1, __shfl_xor_sync(0xffffffffu, rmax1, off));
        }
        float mn0 = fmaxf(m0r, rmax0), mn1 = fmaxf(m1r, rmax1);
        float al0 = __expf(m0r - mn0), al1 = __expf(m1r - mn1);
        m0r = mn0; m1r = mn1;

        float rs0 = 0.f, rs1 = 0.f;
#pragma unroll
        for (int nt = 0; nt < 8; nt++) {
            sacc[nt][0] = __expf(sacc[nt][0] - mn0);
            sacc[nt][1] = __expf(sacc[nt][1] - mn0);
            sacc[nt][2] = __expf(sacc[nt][2] - mn1);
            sacc[nt][3] = __expf(sacc[nt][3] - mn1);
            rs0 += sacc[nt][0] + sacc[nt][1];
            rs1 += sacc[nt][2] + sacc[nt][3];
        }
#pragma unroll
        for (int off = 1; off < 4; off <<= 1) {
            rs0 += __shfl_xor_sync(0xffffffffu, rs0, off);
            rs1 += __shfl_xor_sync(0xffffffffu, rs1, off);
        }
        l0 = l0 * al0 + rs0;
        l1 = l1 * al1 + rs1;
#pragma unroll
        for (int nt = 0; nt < 16; nt++) {
            o[nt][0] *= al0; o[nt][1] *= al0;
            o[nt][2] *= al1; o[nt][3] *= al1;
        }

#pragma unroll
        for (int kc = 0; kc < 4; kc++) {
            uint32_t ph[4], pl[4];
            {
                __half2 l2;
                __half2 h2 = split_pair(sacc[2*kc][0], sacc[2*kc][1], l2);
                ph[0] = *(uint32_t*)&h2; pl[0] = *(uint32_t*)&l2;
                h2 = split_pair(sacc[2*kc][2], sacc[2*kc][3], l2);
                ph[1] = *(uint32_t*)&h2; pl[1] = *(uint32_t*)&l2;
                h2 = split_pair(sacc[2*kc+1][0], sacc[2*kc+1][1], l2);
                ph[2] = *(uint32_t*)&h2; pl[2] = *(uint32_t*)&l2;
                h2 = split_pair(sacc[2*kc+1][2], sacc[2*kc+1][3], l2);
                ph[3] = *(uint32_t*)&h2; pl[3] = *(uint32_t*)&l2;
            }
#pragma unroll
            for (int p = 0; p < 8; p++) {
                int n = p * 16 + b_nl;
                int cf = 2 * kc + b_gs;
                uint32_t va = sb + FV_OFF + n * 128 + ((cf ^ (n & 7)) << 4);
                uint32_t bh[4], bl[4];
                LDSM4(bh[0], bh[1], bh[2], bh[3], va);
                LDSM4(bl[0], bl[1], bl[2], bl[3], va + 16384);
                MMA16816(o[2 * p],     ph, bh[0], bh[1]);
                MMA16816(o[2 * p + 1], ph, bh[2], bh[3]);
                MMA16816(o[2 * p],     ph, bl[0], bl[1]);
                MMA16816(o[2 * p + 1], ph, bl[2], bl[3]);
                MMA16816(o[2 * p],     pl, bh[0], bh[1]);
                MMA16816(o[2 * p + 1], pl, bh[2], bh[3]);
            }
        }
    }

    // ---- epilogue: normalize + split fp16 out ----
    float inv0 = 1.f / l0, inv1 = 1.f / l1;
    int rg0 = q0 + warp * 16 + (lane >> 2);
#pragma unroll
    for (int nt = 0; nt < 16; nt++) {
        int col = h * HDIM + nt * 8 + (lane & 3) * 2;
        {
            __half2 lo2, hi2 = split_pair(o[nt][0] * inv0, o[nt][1] * inv0, lo2);
            *(__half2*)(Oh + (size_t)rg0 * D_MODEL + col) = hi2;
            *(__half2*)(Ol + (size_t)rg0 * D_MODEL + col) = lo2;
        }
        {
            __half2 lo2, hi2 = split_pair(o[nt][2] * inv1, o[nt][3] * inv1, lo2);
            *(__half2*)(Oh + (size_t)(rg0 + 8) * D_MODEL + col) = hi2;
            *(__half2*)(Ol + (size_t)(rg0 + 8) * D_MODEL + col) = lo2;
        }
    }
}

// ---------------------------------------------------------------------------
extern "C" void kernel_launch(void* const* d_in, const int* in_sizes, int n_in,
                              void* d_out, int out_size) {
    const float* x  = (const float*)d_in[0];
    const float* fc = (const float*)d_in[1];
    const float* fs = (const float*)d_in[2];
    const float* wq = (const float*)d_in[4];
    const float* wk = (const float*)d_in[5];
    const float* wv = (const float*)d_in[6];
    const float* wo = (const float*)d_in[7];
    float* out = (float*)d_out;

    float* vp;
    cudaGetSymbolAddress((void**)&vp, g_V);

    __half *xh, *xl, *wqh, *wql, *wkh, *wkl, *wvh, *wvl, *woh, *wol, *ah, *al;
    __half *qfh, *qfl, *kfh, *kfl, *vth, *vtl;
    cudaGetSymbolAddress((void**)&xh,  g_xh);  cudaGetSymbolAddress((void**)&xl,  g_xl);
    cudaGetSymbolAddress((void**)&wqh, g_wqh); cudaGetSymbolAddress((void**)&wql, g_wql);
    cudaGetSymbolAddress((void**)&wkh, g_wkh); cudaGetSymbolAddress((void**)&wkl, g_wkl);
    cudaGetSymbolAddress((void**)&wvh, g_wvh); cudaGetSymbolAddress((void**)&wvl, g_wvl);
    cudaGetSymbolAddress((void**)&woh, g_woh); cudaGetSymbolAddress((void**)&wol, g_wol);
    cudaGetSymbolAddress((void**)&ah,  g_ah);  cudaGetSymbolAddress((void**)&al,  g_al);
    cudaGetSymbolAddress((void**)&qfh, g_Qfh); cudaGetSymbolAddress((void**)&qfl, g_Qfl);
    cudaGetSymbolAddress((void**)&kfh, g_Kfh); cudaGetSymbolAddress((void**)&kfl, g_Kfl);
    cudaGetSymbolAddress((void**)&vth, g_Vth); cudaGetSymbolAddress((void**)&vtl, g_Vtl);

    cudaFuncSetAttribute((const void*)hgemm_split<0>,
                         cudaFuncAttributeMaxDynamicSharedMemorySize, HGEMM_SMEM);
    cudaFuncSetAttribute((const void*)hgemm_split<1>,
                         cudaFuncAttributeMaxDynamicSharedMemorySize, HGEMM_SMEM);
    cudaFuncSetAttribute((const void*)flash_tc,
                         cudaFuncAttributeMaxDynamicSharedMemorySize, FLASH_TC_SMEM);

    const int NX  = S_LEN * D_MODEL;
    const int NW  = D_MODEL * D_MODEL;
    const int NKW = KV_D * D_MODEL;

    split_h<<<(NX  + 255) / 256, 256>>>(x,  xh,  xl,  NX);
    split_h<<<(NW  + 255) / 256, 256>>>(wq, wqh, wql, NW);
    split_h<<<(NKW + 255) / 256, 256>>>(wk, wkh, wkl, NKW);
    split_h<<<(NKW + 255) / 256, 256>>>(wv, wvh, wvl, NKW);
    split_h<<<(NW  + 255) / 256, 256>>>(wo, woh, wol, NW);

    // Q/K projections with fused rope+scale+split epilogue
    hgemm_split<1><<<dim3(32, 16), 256, HGEMM_SMEM>>>(
        xh, xl, wqh, wql, nullptr, qfh, qfl, fc, fs, ATT_SCALE,
        S_LEN, NH * HDIM, D_MODEL);
    hgemm_split<1><<<dim3(8, 16), 256, HGEMM_SMEM>>>(
        xh, xl, wkh, wkl, nullptr, kfh, kfl, fc, fs, 1.f,
        S_LEN, KV_D, D_MODEL);
    // V projection (fp32 out) + transpose/split
    hgemm_split<0><<<dim3(8, 16), 256, HGEMM_SMEM>>>(
        xh, xl, wvh, wvl, vp, nullptr, nullptr, nullptr, nullptr, 1.f,
        S_LEN, KV_D, D_MODEL);
    transpose_split_v<<<dim3(S_LEN / 32, KV_D / 32), dim3(32, 8)>>>(vp, vth, vtl);

    // Flash attention (tensor cores), split fp16 out
    flash_tc<<<dim3(32, 32), 128, FLASH_TC_SMEM>>>(qfh, qfl, kfh, kfl, vth, vtl,
                                                   ah, al);

    // Output projection (fp32 out)
    hgemm_split<0><<<dim3(32, 16), 256, HGEMM_SMEM>>>(
        ah, al, woh, wol, out, nullptr, nullptr, nullptr, nullptr, 1.f,
        S_LEN, D_MODEL, D_MODEL);
}

// round 9
// speedup vs baseline: 4.2148x; 1.2917x over previous
#include <cuda_runtime.h>
#include <cuda_fp16.h>
#include <math.h>
#include <stdint.h>

#define S_LEN   2048
#define D_MODEL 4096
#define NH      32
#define NKV     8
#define HDIM    128
#define KV_D    (NKV * HDIM)           // 1024
#define ATT_SCALE 0.08838834764831843f // 128^-0.5

// ---------------- static scratch (allocation forbidden) --------------------
__device__ float g_V[S_LEN * KV_D];

__device__ __half g_xh[S_LEN * D_MODEL],  g_xl[S_LEN * D_MODEL];
__device__ __half g_wqh[D_MODEL * D_MODEL];
__device__ __half g_wkh[KV_D * D_MODEL];
__device__ __half g_wvh[KV_D * D_MODEL];
__device__ __half g_woh[D_MODEL * D_MODEL];
__device__ __half g_ah[S_LEN * D_MODEL], g_al[S_LEN * D_MODEL];

__device__ __half g_Qfh[S_LEN * D_MODEL], g_Qfl[S_LEN * D_MODEL];  // rope'd, scaled
__device__ __half g_Kfh[S_LEN * KV_D],    g_Kfl[S_LEN * KV_D];     // rope'd
__device__ __half g_Vth[KV_D * S_LEN],    g_Vtl[KV_D * S_LEN];     // [kvh*128+d][s]

// ---------------------------------------------------------------------------
__device__ __forceinline__ void cp16(uint32_t dst, const void* src) {
    asm volatile("cp.async.cg.shared.global [%0], [%1], 16;\n" :: "r"(dst), "l"(src));
}
#define LDSM4(R0, R1, R2, R3, ADDR)                                          \
    asm volatile("ldmatrix.sync.aligned.m8n8.x4.shared.b16 {%0,%1,%2,%3},[%4];" \
                 : "=r"(R0), "=r"(R1), "=r"(R2), "=r"(R3) : "r"(ADDR))
#define MMA16816(C, A, B0, B1)                                               \
    asm volatile("mma.sync.aligned.m16n8k16.row.col.f32.f16.f16.f32 "        \
                 "{%0,%1,%2,%3},{%4,%5,%6,%7},{%8,%9},{%0,%1,%2,%3};"        \
                 : "+f"((C)[0]), "+f"((C)[1]), "+f"((C)[2]), "+f"((C)[3])    \
                 : "r"((A)[0]), "r"((A)[1]), "r"((A)[2]), "r"((A)[3]),       \
                   "r"(B0), "r"(B1))

__device__ __forceinline__ __half2 split_pair(float a, float b, __half2& lo) {
    __half ah = __float2half_rn(a), bh = __float2half_rn(b);
    lo = __halves2half2(__float2half_rn(a - __half2float(ah)),
                        __float2half_rn(b - __half2float(bh)));
    return __halves2half2(ah, bh);
}

// ---------------------------------------------------------------------------
__global__ void split_h(const float* __restrict__ in,
                        __half* __restrict__ hi, __half* __restrict__ lo, int n) {
    int i = blockIdx.x * blockDim.x + threadIdx.x;
    if (i >= n) return;
    float a = in[i];
    __half h = __float2half_rn(a);
    hi[i] = h;
    lo[i] = __float2half_rn(a - __half2float(h));
}

__global__ void cvt_h(const float* __restrict__ in, __half* __restrict__ hi, int n) {
    int i = blockIdx.x * blockDim.x + threadIdx.x;
    if (i >= n) return;
    hi[i] = __float2half_rn(in[i]);
}

// ---------------------------------------------------------------------------
__global__ void transpose_split_v(const float* __restrict__ V,
                                  __half* __restrict__ Vth,
                                  __half* __restrict__ Vtl) {
    __shared__ float tile[32][33];
    const int s0 = blockIdx.x * 32, d0 = blockIdx.y * 32;
    const int tx = threadIdx.x, ty = threadIdx.y;
#pragma unroll
    for (int i = 0; i < 4; i++)
        tile[ty + 8 * i][tx] = V[(size_t)(s0 + ty + 8 * i) * KV_D + d0 + tx];
    __syncthreads();
#pragma unroll
    for (int i = 0; i < 4; i++) {
        int d = d0 + ty + 8 * i, s = s0 + tx;
        float v = tile[tx][ty + 8 * i];
        __half h = __float2half_rn(v);
        Vth[(size_t)d * S_LEN + s] = h;
        Vtl[(size_t)d * S_LEN + s] = __float2half_rn(v - __half2float(h));
    }
}

// ---------------------------------------------------------------------------
// HGEMM 2-term split: C = (Ah + Al) @ Bh^T, fp32 accum.
// MODE 0: fp32 C out. MODE 1: rope+scale+split-fp16 out.
// 128x128 tile, k32, 3-stage cp.async ring, 256 threads, 2 CTAs/SM.
// ---------------------------------------------------------------------------
#define HGEMM_SMEM (3 * 32768)

template<int MODE>
__global__ __launch_bounds__(256, 2)
void hgemm_split(const __half* __restrict__ Ah, const __half* __restrict__ Al,
                 const __half* __restrict__ Bh,
                 float* __restrict__ C,
                 __half* __restrict__ Hi, __half* __restrict__ Lo,
                 const float* __restrict__ cosw, const float* __restrict__ sinw,
                 float scale, int M, int N, int K) {
    extern __shared__ __half smh[];
    const uint32_t sbase = (uint32_t)__cvta_generic_to_shared(smh);

    const int t    = threadIdx.x;
    const int m0   = blockIdx.y * 128;
    const int n0   = blockIdx.x * 128;
    const int warp = t >> 5;
    const int lane = t & 31;
    const int wm   = (warp >> 1) * 32;
    const int wn   = (warp & 1) * 64;

    const int a_mloc = lane & 15;
    const int a_gsel = lane >> 4;
    const int b_nloc = (lane & 7) + ((lane & 16) >> 1);
    const int b_gsel = (lane >> 3) & 1;

    float acc[2][8][4];
#pragma unroll
    for (int mt = 0; mt < 2; mt++)
#pragma unroll
        for (int nt = 0; nt < 8; nt++)
#pragma unroll
            for (int r = 0; r < 4; r++) acc[mt][nt][r] = 0.f;

    // stage: A (hi sg0-3, lo sg4-7) 16KB at abase; B (hi sg0-3) at bbase
    auto issue = [&](int k0, int buf) {
        uint32_t abase = sbase + buf * 32768;
        uint32_t bbase = abase + 16384;
#pragma unroll
        for (int i = 0; i < 4; i++) {
            int ga = t + i * 256;
            int m = ga >> 3, sg = ga & 7;
            const __half* src = (sg < 4 ? Ah : Al)
                              + (size_t)(m0 + m) * K + k0 + (sg & 3) * 8;
            cp16(abase + m * 128 + ((sg ^ (m & 7)) << 4), src);
        }
#pragma unroll
        for (int i = 0; i < 2; i++) {
            int ga = t + i * 256;
            int n = ga >> 2, sg = ga & 3;
            const __half* src = Bh + (size_t)(n0 + n) * K + k0 + sg * 8;
            cp16(bbase + n * 128 + ((sg ^ (n & 7)) << 4), src);
        }
    };

    const int NIT = K >> 5;
    issue(0, 0);
    asm volatile("cp.async.commit_group;");
    issue(32, 1);
    asm volatile("cp.async.commit_group;");

    for (int it = 0; it < NIT; it++) {
        if (it + 2 < NIT) {
            issue((it + 2) << 5, (it + 2) % 3);
            asm volatile("cp.async.commit_group;");
            asm volatile("cp.async.wait_group 2;");
        } else if (it + 1 < NIT) {
            asm volatile("cp.async.wait_group 1;");
        } else {
            asm volatile("cp.async.wait_group 0;");
        }
        __syncthreads();

        const uint32_t abase = sbase + (it % 3) * 32768;
        const uint32_t bbase = abase + 16384;

#pragma unroll
        for (int c = 0; c < 2; c++) {
            uint32_t ah[2][4], al[2][4], bb[4][4];
#pragma unroll
            for (int mt = 0; mt < 2; mt++) {
                int m = wm + mt * 16 + a_mloc;
                int sg = 2 * c + a_gsel;
                LDSM4(ah[mt][0], ah[mt][1], ah[mt][2], ah[mt][3],
                      abase + m * 128 + ((sg ^ (m & 7)) << 4));
            }
#pragma unroll
            for (int p = 0; p < 4; p++) {
                int n = wn + p * 16 + b_nloc;
                int sg = 2 * c + b_gsel;
                LDSM4(bb[p][0], bb[p][1], bb[p][2], bb[p][3],
                      bbase + n * 128 + ((sg ^ (n & 7)) << 4));
            }
#pragma unroll
            for (int mt = 0; mt < 2; mt++)
#pragma unroll
                for (int p = 0; p < 4; p++) {
                    MMA16816(acc[mt][2 * p],     ah[mt], bb[p][0], bb[p][1]);
                    MMA16816(acc[mt][2 * p + 1], ah[mt], bb[p][2], bb[p][3]);
                }
#pragma unroll
            for (int mt = 0; mt < 2; mt++) {
                int m = wm + mt * 16 + a_mloc;
                int sg = 4 + 2 * c + a_gsel;
                LDSM4(al[mt][0], al[mt][1], al[mt][2], al[mt][3],
                      abase + m * 128 + ((sg ^ (m & 7)) << 4));
            }
#pragma unroll
            for (int mt = 0; mt < 2; mt++)
#pragma unroll
                for (int p = 0; p < 4; p++) {
                    MMA16816(acc[mt][2 * p],     al[mt], bb[p][0], bb[p][1]);
                    MMA16816(acc[mt][2 * p + 1], al[mt], bb[p][2], bb[p][3]);
                }
        }
        __syncthreads();
    }

    // ---- epilogue ----
#pragma unroll
    for (int mt = 0; mt < 2; mt++) {
        int r = m0 + wm + mt * 16 + (lane >> 2);
#pragma unroll
        for (int nt = 0; nt < 8; nt++) {
            int cc = n0 + wn + nt * 8 + (lane & 3) * 2;
            if (MODE == 0) {
                float* p0 = C + (size_t)r * N + cc;
                p0[0] = acc[mt][nt][0];
                p0[1] = acc[mt][nt][1];
                float* p1 = p0 + 8 * N;
                p1[0] = acc[mt][nt][2];
                p1[1] = acc[mt][nt][3];
            } else {
                int i = (cc & 127) >> 1;
                {
                    float cw = cosw[r * 64 + i], sw = sinw[r * 64 + i];
                    float t0 = acc[mt][nt][0], t1 = acc[mt][nt][1];
                    float r0 = (t0 * cw - t1 * sw) * scale;
                    float r1 = (t0 * sw + t1 * cw) * scale;
                    __half2 lo2, hi2 = split_pair(r0, r1, lo2);
                    *(__half2*)(Hi + (size_t)r * N + cc) = hi2;
                    *(__half2*)(Lo + (size_t)r * N + cc) = lo2;
                }
                {
                    int r8 = r + 8;
                    float cw = cosw[r8 * 64 + i], sw = sinw[r8 * 64 + i];
                    float t0 = acc[mt][nt][2], t1 = acc[mt][nt][3];
                    float r0 = (t0 * cw - t1 * sw) * scale;
                    float r1 = (t0 * sw + t1 * cw) * scale;
                    __half2 lo2, hi2 = split_pair(r0, r1, lo2);
                    *(__half2*)(Hi + (size_t)r8 * N + cc) = hi2;
                    *(__half2*)(Lo + (size_t)r8 * N + cc) = lo2;
                }
            }
        }
    }
}

// ---------------------------------------------------------------------------
// Flash attention on tensor cores (split-fp16, 3-term), split-fp16 output.
// ---------------------------------------------------------------------------
#define FQ_OFF  0
#define FK_OFF  32768
#define FV_OFF  65536
#define FLASH_TC_SMEM 98304

__global__ __launch_bounds__(128, 1)
void flash_tc(const __half* __restrict__ Qh, const __half* __restrict__ Ql,
              const __half* __restrict__ Kh, const __half* __restrict__ Kl,
              const __half* __restrict__ Vth, const __half* __restrict__ Vtl,
              __half* __restrict__ Oh, __half* __restrict__ Ol) {
    extern __shared__ char smc[];
    const uint32_t sb = (uint32_t)__cvta_generic_to_shared(smc);
    const int t    = threadIdx.x;
    const int lane = t & 31;
    const int warp = t >> 5;
    const int qt   = (int)gridDim.x - 1 - (int)blockIdx.x;
    const int h    = blockIdx.y;
    const int kh   = h >> 2;
    const int q0   = qt * 64;

    const int a_ml = lane & 15;
    const int a_gs = lane >> 4;
    const int b_nl = (lane & 7) + ((lane & 16) >> 1);
    const int b_gs = (lane >> 3) & 1;

#pragma unroll
    for (int i = 0; i < 16; i++) {
        int g = t + i * 128;
        int half = g >> 10, gg = g & 1023;
        int r = gg >> 4, c = gg & 15;
        const __half* src = (half ? Ql : Qh)
                          + (size_t)(q0 + r) * D_MODEL + h * HDIM + c * 8;
        cp16(sb + FQ_OFF + half * 16384 + r * 256 + ((c ^ (r & 7)) << 4), src);
    }
    asm volatile("cp.async.commit_group;");

    float o[16][4];
#pragma unroll
    for (int nt = 0; nt < 16; nt++)
#pragma unroll
        for (int j = 0; j < 4; j++) o[nt][j] = 0.f;
    float m0r = -1e30f, m1r = -1e30f, l0 = 0.f, l1 = 0.f;

    for (int kt = 0; kt <= qt; kt++) {
        const int k0 = kt * 64;
        __syncthreads();
#pragma unroll
        for (int i = 0; i < 16; i++) {
            int g = t + i * 128;
            int half = g >> 10, gg = g & 1023;
            int r = gg >> 4, c = gg & 15;
            const __half* src = (half ? Kl : Kh)
                              + (size_t)(k0 + r) * KV_D + kh * HDIM + c * 8;
            cp16(sb + FK_OFF + half * 16384 + r * 256 + ((c ^ (r & 7)) << 4), src);
        }
#pragma unroll
        for (int i = 0; i < 16; i++) {
            int g = t + i * 128;
            int half = g >> 10, gg = g & 1023;
            int r = gg >> 3, c = gg & 7;
            const __half* src = (half ? Vtl : Vth)
                              + (size_t)(kh * HDIM + r) * S_LEN + k0 + c * 8;
            cp16(sb + FV_OFF + half * 16384 + r * 128 + ((c ^ (r & 7)) << 4), src);
        }
        asm volatile("cp.async.commit_group;");
        asm volatile("cp.async.wait_group 0;");
        __syncthreads();

        float sacc[8][4];
#pragma unroll
        for (int nt = 0; nt < 8; nt++)
#pragma unroll
            for (int j = 0; j < 4; j++) sacc[nt][j] = 0.f;

#pragma unroll
        for (int kc = 0; kc < 8; kc++) {
            uint32_t aqh[4], aql[4];
            {
                int r = warp * 16 + a_ml;
                int cf = 2 * kc + a_gs;
                uint32_t qa = sb + FQ_OFF + r * 256 + ((cf ^ (r & 7)) << 4);
                LDSM4(aqh[0], aqh[1], aqh[2], aqh[3], qa);
                LDSM4(aql[0], aql[1], aql[2], aql[3], qa + 16384);
            }
#pragma unroll
            for (int p = 0; p < 4; p++) {
                int n = p * 16 + b_nl;
                int cf = 2 * kc + b_gs;
                uint32_t ka = sb + FK_OFF + n * 256 + ((cf ^ (n & 7)) << 4);
                uint32_t bh[4], bl[4];
                LDSM4(bh[0], bh[1], bh[2], bh[3], ka);
                LDSM4(bl[0], bl[1], bl[2], bl[3], ka + 16384);
                MMA16816(sacc[2 * p],     aqh, bh[0], bh[1]);
                MMA16816(sacc[2 * p + 1], aqh, bh[2], bh[3]);
                MMA16816(sacc[2 * p],     aqh, bl[0], bl[1]);
                MMA16816(sacc[2 * p + 1], aqh, bl[2], bl[3]);
                MMA16816(sacc[2 * p],     aql, bh[0], bh[1]);
                MMA16816(sacc[2 * p + 1], aql, bh[2], bh[3]);
            }
        }

        if (kt == qt) {
            int rg0 = q0 + warp * 16 + (lane >> 2);
#pragma unroll
            for (int nt = 0; nt < 8; nt++) {
                int cg = k0 + nt * 8 + (lane & 3) * 2;
                if (cg     > rg0)     sacc[nt][0] += -1e9f;
                if (cg + 1 > rg0)     sacc[nt][1] += -1e9f;
                if (cg     > rg0 + 8) sacc[nt][2] += -1e9f;
                if (cg + 1 > rg0 + 8) sacc[nt][3] += -1e9f;
            }
        }

        float rmax0 = -1e30f, rmax1 = -1e30f;
#pragma unroll
        for (int nt = 0; nt < 8; nt++) {
            rmax0 = fmaxf(rmax0, fmaxf(sacc[nt][0], sacc[nt][1]));
            rmax1 = fmaxf(rmax1, fmaxf(sacc[nt][2], sacc[nt][3]));
        }
#pragma unroll
        for (int off = 1; off < 4; off <<= 1) {
            rmax0 = fmaxf(rmax0, __shfl_xor_sync(0xffffffffu, rmax0, off));
            rmax1 = fmaxf(rmax1, __shfl_xor_sync(0xffffffffu, rmax1, off));
        }
        float mn0 = fmaxf(m0r, rmax0), mn1 = fmaxf(m1r, rmax1);
        float al0 = __expf(m0r - mn0), al1 = __expf(m1r - mn1);
        m0r = mn0; m1r = mn1;

        float rs0 = 0.f, rs1 = 0.f;
#pragma unroll
        for (int nt = 0; nt < 8; nt++) {
            sacc[nt][0] = __expf(sacc[nt][0] - mn0);
            sacc[nt][1] = __expf(sacc[nt][1] - mn0);
            sacc[nt][2] = __expf(sacc[nt][2] - mn1);
            sacc[nt][3] = __expf(sacc[nt][3] - mn1);
            rs0 += sacc[nt][0] + sacc[nt][1];
            rs1 += sacc[nt][2] + sacc[nt][3];
        }
#pragma unroll
        for (int off = 1; off < 4; off <<= 1) {
            rs0 += __shfl_xor_sync(0xffffffffu, rs0, off);
            rs1 += __shfl_xor_sync(0xffffffffu, rs1, off);
        }
        l0 = l0 * al0 + rs0;
        l1 = l1 * al1 + rs1;
#pragma unroll
        for (int nt = 0; nt < 16; nt++) {
            o[nt][0] *= al0; o[nt][1] *= al0;
            o[nt][2] *= al1; o[nt][3] *= al1;
        }

#pragma unroll
        for (int kc = 0; kc < 4; kc++) {
            uint32_t ph[4], pl[4];
            {
                __half2 l2;
                __half2 h2 = split_pair(sacc[2*kc][0], sacc[2*kc][1], l2);
                ph[0] = *(uint32_t*)&h2; pl[0] = *(uint32_t*)&l2;
                h2 = split_pair(sacc[2*kc][2], sacc[2*kc][3], l2);
                ph[1] = *(uint32_t*)&h2; pl[1] = *(uint32_t*)&l2;
                h2 = split_pair(sacc[2*kc+1][0], sacc[2*kc+1][1], l2);
                ph[2] = *(uint32_t*)&h2; pl[2] = *(uint32_t*)&l2;
                h2 = split_pair(sacc[2*kc+1][2], sacc[2*kc+1][3], l2);
                ph[3] = *(uint32_t*)&h2; pl[3] = *(uint32_t*)&l2;
            }
#pragma unroll
            for (int p = 0; p < 8; p++) {
                int n = p * 16 + b_nl;
                int cf = 2 * kc + b_gs;
                uint32_t va = sb + FV_OFF + n * 128 + ((cf ^ (n & 7)) << 4);
                uint32_t bh[4], bl[4];
                LDSM4(bh[0], bh[1], bh[2], bh[3], va);
                LDSM4(bl[0], bl[1], bl[2], bl[3], va + 16384);
                MMA16816(o[2 * p],     ph, bh[0], bh[1]);
                MMA16816(o[2 * p + 1], ph, bh[2], bh[3]);
                MMA16816(o[2 * p],     ph, bl[0], bl[1]);
                MMA16816(o[2 * p + 1], ph, bl[2], bl[3]);
                MMA16816(o[2 * p],     pl, bh[0], bh[1]);
                MMA16816(o[2 * p + 1], pl, bh[2], bh[3]);
            }
        }
    }

    float inv0 = 1.f / l0, inv1 = 1.f / l1;
    int rg0 = q0 + warp * 16 + (lane >> 2);
#pragma unroll
    for (int nt = 0; nt < 16; nt++) {
        int col = h * HDIM + nt * 8 + (lane & 3) * 2;
        {
            __half2 lo2, hi2 = split_pair(o[nt][0] * inv0, o[nt][1] * inv0, lo2);
            *(__half2*)(Oh + (size_t)rg0 * D_MODEL + col) = hi2;
            *(__half2*)(Ol + (size_t)rg0 * D_MODEL + col) = lo2;
        }
        {
            __half2 lo2, hi2 = split_pair(o[nt][2] * inv1, o[nt][3] * inv1, lo2);
            *(__half2*)(Oh + (size_t)(rg0 + 8) * D_MODEL + col) = hi2;
            *(__half2*)(Ol + (size_t)(rg0 + 8) * D_MODEL + col) = lo2;
        }
    }
}

// ---------------------------------------------------------------------------
extern "C" void kernel_launch(void* const* d_in, const int* in_sizes, int n_in,
                              void* d_out, int out_size) {
    const float* x  = (const float*)d_in[0];
    const float* fc = (const float*)d_in[1];
    const float* fs = (const float*)d_in[2];
    const float* wq = (const float*)d_in[4];
    const float* wk = (const float*)d_in[5];
    const float* wv = (const float*)d_in[6];
    const float* wo = (const float*)d_in[7];
    float* out = (float*)d_out;

    float* vp;
    cudaGetSymbolAddress((void**)&vp, g_V);

    __half *xh, *xl, *wqh, *wkh, *wvh, *woh, *ah, *al;
    __half *qfh, *qfl, *kfh, *kfl, *vth, *vtl;
    cudaGetSymbolAddress((void**)&xh,  g_xh);  cudaGetSymbolAddress((void**)&xl,  g_xl);
    cudaGetSymbolAddress((void**)&wqh, g_wqh);
    cudaGetSymbolAddress((void**)&wkh, g_wkh);
    cudaGetSymbolAddress((void**)&wvh, g_wvh);
    cudaGetSymbolAddress((void**)&woh, g_woh);
    cudaGetSymbolAddress((void**)&ah,  g_ah);  cudaGetSymbolAddress((void**)&al,  g_al);
    cudaGetSymbolAddress((void**)&qfh, g_Qfh); cudaGetSymbolAddress((void**)&qfl, g_Qfl);
    cudaGetSymbolAddress((void**)&kfh, g_Kfh); cudaGetSymbolAddress((void**)&kfl, g_Kfl);
    cudaGetSymbolAddress((void**)&vth, g_Vth); cudaGetSymbolAddress((void**)&vtl, g_Vtl);

    cudaFuncSetAttribute((const void*)hgemm_split<0>,
                         cudaFuncAttributeMaxDynamicSharedMemorySize, HGEMM_SMEM);
    cudaFuncSetAttribute((const void*)hgemm_split<1>,
                         cudaFuncAttributeMaxDynamicSharedMemorySize, HGEMM_SMEM);
    cudaFuncSetAttribute((const void*)flash_tc,
                         cudaFuncAttributeMaxDynamicSharedMemorySize, FLASH_TC_SMEM);

    const int NX  = S_LEN * D_MODEL;
    const int NW  = D_MODEL * D_MODEL;
    const int NKW = KV_D * D_MODEL;

    split_h<<<(NX + 255) / 256, 256>>>(x, xh, xl, NX);
    cvt_h<<<(NW  + 255) / 256, 256>>>(wq, wqh, NW);
    cvt_h<<<(NKW + 255) / 256, 256>>>(wk, wkh, NKW);
    cvt_h<<<(NKW + 255) / 256, 256>>>(wv, wvh, NKW);
    cvt_h<<<(NW  + 255) / 256, 256>>>(wo, woh, NW);

    // Q/K projections with fused rope+scale+split epilogue
    hgemm_split<1><<<dim3(32, 16), 256, HGEMM_SMEM>>>(
        xh, xl, wqh, nullptr, qfh, qfl, fc, fs, ATT_SCALE,
        S_LEN, NH * HDIM, D_MODEL);
    hgemm_split<1><<<dim3(8, 16), 256, HGEMM_SMEM>>>(
        xh, xl, wkh, nullptr, kfh, kfl, fc, fs, 1.f,
        S_LEN, KV_D, D_MODEL);
    // V projection + transpose/split
    hgemm_split<0><<<dim3(8, 16), 256, HGEMM_SMEM>>>(
        xh, xl, wvh, vp, nullptr, nullptr, nullptr, nullptr, 1.f,
        S_LEN, KV_D, D_MODEL);
    transpose_split_v<<<dim3(S_LEN / 32, KV_D / 32), dim3(32, 8)>>>(vp, vth, vtl);

    // Flash attention (tensor cores, 3-term), split-fp16 out
    flash_tc<<<dim3(32, 32), 128, FLASH_TC_SMEM>>>(qfh, qfl, kfh, kfl, vth, vtl,
                                                   ah, al);

    // Output projection (2-term)
    hgemm_split<0><<<dim3(32, 16), 256, HGEMM_SMEM>>>(
        ah, al, woh, out, nullptr, nullptr, nullptr, nullptr, 1.f,
        S_LEN, D_MODEL, D_MODEL);
}